// round 1
// baseline (speedup 1.0000x reference)
#include <cuda_runtime.h>
#include <math.h>

// ---------------- problem constants ----------------
#define Bn    2
#define Ln    2048
#define Dn    2048
#define DINn  4096
#define Nn    128
#define Hn    64
#define Pn    64
#define Kc    4
#define CONVD 4352            // DIN + 2*G*N
#define Qn    64
#define NCn   32
#define PROJW 8512            // 2*DIN + 2*G*N + H
#define BLn   (Bn*Ln)         // 4096
#define EPSf  1e-5f

// ---------------- scratch (static device memory; no allocs allowed) ----------------
__device__ float g_h[(size_t)BLn*Dn];                      // normalized input
__device__ float g_proj[(size_t)BLn*PROJW];                // in_proj output
__device__ float g_xbc[(size_t)BLn*CONVD];                 // conv+silu output
__device__ float g_dt[(size_t)BLn*Hn];
__device__ float g_a[(size_t)BLn*Hn];
__device__ float g_acs[(size_t)BLn*Hn];                    // within-chunk cumsum of a
__device__ float g_csum[(size_t)Bn*Hn*NCn];                // chunk totals
__device__ float g_states[(size_t)Bn*Hn*NCn*Pn*Nn];       // per-chunk local states
__device__ float g_statein[(size_t)Bn*Hn*NCn*Pn*Nn];      // state entering each chunk
__device__ float g_y[(size_t)BLn*DINn];                    // SSD output (pre gate-norm)
__device__ float g_yg[(size_t)BLn*DINn];                   // gated+normed

// ---------------- helpers ----------------
__device__ __forceinline__ float block_reduce_sum(float v) {
    __shared__ float red[32];
    int lane = threadIdx.x & 31, wid = threadIdx.x >> 5;
    #pragma unroll
    for (int o = 16; o; o >>= 1) v += __shfl_down_sync(0xffffffffu, v, o);
    if (lane == 0) red[wid] = v;
    __syncthreads();
    v = (threadIdx.x < (blockDim.x >> 5)) ? red[threadIdx.x] : 0.f;
    if (wid == 0) {
        #pragma unroll
        for (int o = 16; o; o >>= 1) v += __shfl_down_sync(0xffffffffu, v, o);
        if (lane == 0) red[0] = v;
    }
    __syncthreads();
    return red[0];
}

__device__ __forceinline__ float siluf(float x) {
    return x / (1.f + expf(-x));
}

// ---------------- 1) resid = hs + residual ; h = rmsnorm(resid)*w ----------------
__global__ __launch_bounds__(256) void k_add_rmsnorm(
    const float* __restrict__ hs, const float* __restrict__ res,
    const float* __restrict__ w, float* __restrict__ resid_out) {
    size_t row = blockIdx.x;
    int t = threadIdx.x;
    const float* ph = hs + row * Dn;
    const float* pr = res + row * Dn;
    float v[8];
    float ss = 0.f;
    #pragma unroll
    for (int i = 0; i < 8; i++) {
        int idx = t + i * 256;
        float x = ph[idx] + pr[idx];
        v[i] = x;
        ss += x * x;
        resid_out[row * Dn + idx] = x;
    }
    float tot = block_reduce_sum(ss);
    float inv = rsqrtf(tot / (float)Dn + EPSf);
    #pragma unroll
    for (int i = 0; i < 8; i++) {
        int idx = t + i * 256;
        g_h[row * Dn + idx] = v[i] * inv * w[idx];
    }
}

// ---------------- generic SGEMM: C[M,N] = A[M,K] @ B[K,N] (row-major) ----------------
// 128x128 block tile, BK=8, 256 threads, 8x8 register microtile. M%128==0, K%8==0 assumed.
__global__ __launch_bounds__(256) void sgemm128(
    const float* __restrict__ A, const float* __restrict__ B, float* __restrict__ C,
    int M, int N, int K) {
    __shared__ float As[8][128];
    __shared__ float Bs[8][132];
    int bx = blockIdx.x, by = blockIdx.y;
    int tid = threadIdx.x;
    int tx = tid & 15, ty = tid >> 4;
    float acc[8][8];
    #pragma unroll
    for (int i = 0; i < 8; i++)
        #pragma unroll
        for (int j = 0; j < 8; j++) acc[i][j] = 0.f;

    int aRow = tid >> 1;
    int aCol = (tid & 1) * 4;
    int bRow = tid >> 5;
    int bCol = (tid & 31) * 4;
    const float* Ab = A + (size_t)by * 128 * K;
    int gcol = bx * 128 + bCol;
    bool bok = (gcol < N);

    for (int k0 = 0; k0 < K; k0 += 8) {
        float4 av = *(const float4*)(Ab + (size_t)aRow * K + k0 + aCol);
        As[aCol + 0][aRow] = av.x;
        As[aCol + 1][aRow] = av.y;
        As[aCol + 2][aRow] = av.z;
        As[aCol + 3][aRow] = av.w;
        float4 bv = bok ? *(const float4*)(B + (size_t)(k0 + bRow) * N + gcol)
                        : make_float4(0.f, 0.f, 0.f, 0.f);
        Bs[bRow][bCol + 0] = bv.x;
        Bs[bRow][bCol + 1] = bv.y;
        Bs[bRow][bCol + 2] = bv.z;
        Bs[bRow][bCol + 3] = bv.w;
        __syncthreads();
        #pragma unroll
        for (int kk = 0; kk < 8; kk++) {
            float ar[8], br[8];
            #pragma unroll
            for (int i = 0; i < 8; i++) ar[i] = As[kk][ty * 8 + i];
            #pragma unroll
            for (int j = 0; j < 8; j++) br[j] = Bs[kk][tx * 8 + j];
            #pragma unroll
            for (int i = 0; i < 8; i++)
                #pragma unroll
                for (int j = 0; j < 8; j++) acc[i][j] = fmaf(ar[i], br[j], acc[i][j]);
        }
        __syncthreads();
    }
    #pragma unroll
    for (int i = 0; i < 8; i++) {
        size_t row = (size_t)by * 128 + ty * 8 + i;
        #pragma unroll
        for (int j = 0; j < 8; j++) {
            int col = bx * 128 + tx * 8 + j;
            if (col < N) C[row * N + col] = acc[i][j];
        }
    }
}

// ---------------- 3) causal depthwise conv (K=4) + bias + silu ----------------
__global__ __launch_bounds__(256) void k_conv(
    const float* __restrict__ cw, const float* __restrict__ cb) {
    size_t idx = (size_t)blockIdx.x * 256 + threadIdx.x;
    if (idx >= (size_t)BLn * CONVD) return;
    int c = (int)(idx % CONVD);
    int bl = (int)(idx / CONVD);
    int l = bl % Ln;
    int b = bl / Ln;
    float acc = cb[c];
    #pragma unroll
    for (int k = 0; k < Kc; k++) {
        int ls = l - (Kc - 1) + k;
        if (ls >= 0)
            acc = fmaf(cw[c * Kc + k],
                       g_proj[((size_t)(b * Ln + ls)) * PROJW + DINn + c], acc);
    }
    g_xbc[idx] = siluf(acc);
}

// ---------------- 4) dt = softplus(dt_raw + bias); a = -exp(A_log)*dt ----------------
__global__ __launch_bounds__(256) void k_dt(
    const float* __restrict__ dtb, const float* __restrict__ alog) {
    int idx = blockIdx.x * 256 + threadIdx.x;
    if (idx >= BLn * Hn) return;
    int h = idx & (Hn - 1);
    int bl = idx / Hn;
    float x = g_proj[(size_t)bl * PROJW + (DINn + CONVD) + h] + dtb[h];
    float sp = (x > 20.f) ? x : log1pf(expf(x));
    g_dt[idx] = sp;
    g_a[idx] = -expf(alog[h]) * sp;
}

// ---------------- 5) per-chunk: cumsum, Y_diag + D*xs, local states ----------------
// grid (NC, H, B), 256 threads, dynamic smem 99840B
__global__ __launch_bounds__(256) void k_chunk(const float* __restrict__ dskip) {
    extern __shared__ float sm[];
    float* Bsm = sm;                  // 64 x 129
    float* Csm = Bsm + 64 * 129;      // 64 x 129
    float* Xd  = Csm + 64 * 129;      // 64 x 65
    float* Ms  = Xd + 64 * 65;        // 64 x 65
    float* Acs = Ms + 64 * 65;        // 64
    float* Dec = Acs + 64;            // 64

    int c = blockIdx.x, h = blockIdx.y, b = blockIdx.z;
    int t = threadIdx.x;
    size_t rowbase = ((size_t)(b * Ln + c * Qn)) * CONVD;

    for (int i = t; i < Qn * Nn; i += 256) {
        int s = i >> 7, n = i & 127;
        size_t g = rowbase + (size_t)s * CONVD + DINn;
        Bsm[s * 129 + n] = g_xbc[g + n];
        Csm[s * 129 + n] = g_xbc[g + Nn + n];
    }
    if (t < Qn) Acs[t] = g_a[(size_t)(b * Ln + c * Qn + t) * Hn + h];
    __syncthreads();
    if (t == 0) {
        float r = 0.f;
        for (int i = 0; i < Qn; i++) { r += Acs[i]; Acs[i] = r; }
    }
    __syncthreads();
    if (t < Qn) {
        float aq = Acs[t];
        Dec[t] = expf(Acs[Qn - 1] - aq);
        g_acs[(size_t)(b * Ln + c * Qn + t) * Hn + h] = aq;
        if (t == Qn - 1) g_csum[(size_t)(b * Hn + h) * NCn + c] = aq;
    }
    for (int i = t; i < Qn * Pn; i += 256) {
        int s = i >> 6, p = i & 63;
        float xs = g_xbc[rowbase + (size_t)s * CONVD + h * Pn + p];
        Xd[s * 65 + p] = xs * g_dt[(size_t)(b * Ln + c * Qn + s) * Hn + h];
    }
    __syncthreads();

    // M[q][s] = (C_q . B_s) * exp(acs[q]-acs[s]) for s<=q else 0
    {
        int qb = t >> 4, sb = t & 15;
        int q0 = qb * 4, s0 = sb * 4;
        float m[4][4];
        #pragma unroll
        for (int i = 0; i < 4; i++)
            #pragma unroll
            for (int j = 0; j < 4; j++) m[i][j] = 0.f;
        if (s0 <= q0 + 3) {
            for (int n = 0; n < Nn; n++) {
                float cq[4], bs[4];
                #pragma unroll
                for (int i = 0; i < 4; i++) cq[i] = Csm[(q0 + i) * 129 + n];
                #pragma unroll
                for (int j = 0; j < 4; j++) bs[j] = Bsm[(s0 + j) * 129 + n];
                #pragma unroll
                for (int i = 0; i < 4; i++)
                    #pragma unroll
                    for (int j = 0; j < 4; j++) m[i][j] = fmaf(cq[i], bs[j], m[i][j]);
            }
        }
        #pragma unroll
        for (int i = 0; i < 4; i++)
            #pragma unroll
            for (int j = 0; j < 4; j++) {
                int q = q0 + i, s = s0 + j;
                Ms[q * 65 + s] = (s <= q) ? m[i][j] * expf(Acs[q] - Acs[s]) : 0.f;
            }
    }
    __syncthreads();

    // Y_diag[q][p] = sum_{s<=q} M[q][s]*Xd[s][p]   (+ D_skip*xs at write)
    {
        int qb = t >> 4, pb = t & 15;
        int q0 = qb * 4, p0 = pb * 4;
        float y4[4][4];
        #pragma unroll
        for (int i = 0; i < 4; i++)
            #pragma unroll
            for (int j = 0; j < 4; j++) y4[i][j] = 0.f;
        int smax = q0 + 3;
        for (int s = 0; s <= smax; s++) {
            float mv[4], xv[4];
            #pragma unroll
            for (int i = 0; i < 4; i++) mv[i] = Ms[(q0 + i) * 65 + s];
            #pragma unroll
            for (int j = 0; j < 4; j++) xv[j] = Xd[s * 65 + p0 + j];
            #pragma unroll
            for (int i = 0; i < 4; i++)
                #pragma unroll
                for (int j = 0; j < 4; j++) y4[i][j] = fmaf(mv[i], xv[j], y4[i][j]);
        }
        float dsk = dskip[h];
        #pragma unroll
        for (int i = 0; i < 4; i++) {
            int q = q0 + i;
            #pragma unroll
            for (int j = 0; j < 4; j++) {
                int p = p0 + j;
                float xs = g_xbc[rowbase + (size_t)q * CONVD + h * Pn + p];
                g_y[((size_t)(b * Ln + c * Qn + q) * Hn + h) * Pn + p] =
                    y4[i][j] + dsk * xs;
            }
        }
    }

    // local state[p][n] = sum_q B[q][n] * exp(acs[Q-1]-acs[q]) * Xd[q][p]
    {
        int pb = t >> 4, nb = t & 15;
        int p0 = pb * 4, n0 = nb * 8;
        float st[4][8];
        #pragma unroll
        for (int i = 0; i < 4; i++)
            #pragma unroll
            for (int j = 0; j < 8; j++) st[i][j] = 0.f;
        for (int q = 0; q < Qn; q++) {
            float d = Dec[q];
            float xv[4], bv[8];
            #pragma unroll
            for (int i = 0; i < 4; i++) xv[i] = Xd[q * 65 + p0 + i] * d;
            #pragma unroll
            for (int j = 0; j < 8; j++) bv[j] = Bsm[q * 129 + n0 + j];
            #pragma unroll
            for (int i = 0; i < 4; i++)
                #pragma unroll
                for (int j = 0; j < 8; j++) st[i][j] = fmaf(xv[i], bv[j], st[i][j]);
        }
        size_t base = ((size_t)(b * Hn + h) * NCn + c) * (Pn * Nn);
        #pragma unroll
        for (int i = 0; i < 4; i++)
            #pragma unroll
            for (int j = 0; j < 8; j++)
                g_states[base + (size_t)(p0 + i) * Nn + n0 + j] = st[i][j];
    }
}

// ---------------- 6) chunk-level scan over NC (per b,h) ----------------
__global__ __launch_bounds__(256) void k_scan() {
    int bh = blockIdx.x;     // 0..B*H-1
    int t = threadIdx.x;
    float S[32];
    #pragma unroll
    for (int k = 0; k < 32; k++) S[k] = 0.f;
    for (int c = 0; c < NCn; c++) {
        size_t base = ((size_t)bh * NCn + c) * (Pn * Nn);
        #pragma unroll
        for (int k = 0; k < 32; k++) g_statein[base + t + k * 256] = S[k];
        float f = expf(g_csum[(size_t)bh * NCn + c]);
        #pragma unroll
        for (int k = 0; k < 32; k++)
            S[k] = fmaf(f, S[k], g_states[base + t + k * 256]);
    }
}

// ---------------- 7) Y_off added into g_y ----------------
// grid (NC, H, B), dynamic smem 66304B
__global__ __launch_bounds__(256) void k_yoff() {
    extern __shared__ float sm[];
    float* Ss  = sm;               // 64 x 129 (p-major)
    float* Csm = Ss + 64 * 129;    // 64 x 129
    float* Eq  = Csm + 64 * 129;   // 64

    int c = blockIdx.x, h = blockIdx.y, b = blockIdx.z;
    int t = threadIdx.x;
    size_t rowbase = ((size_t)(b * Ln + c * Qn)) * CONVD;
    size_t sbase = ((size_t)(b * Hn + h) * NCn + c) * (Pn * Nn);

    for (int i = t; i < Pn * Nn; i += 256) {
        int p = i >> 7, n = i & 127;
        Ss[p * 129 + n] = g_statein[sbase + i];
    }
    for (int i = t; i < Qn * Nn; i += 256) {
        int q = i >> 7, n = i & 127;
        Csm[q * 129 + n] = g_xbc[rowbase + (size_t)q * CONVD + DINn + Nn + n];
    }
    if (t < Qn)
        Eq[t] = expf(g_acs[(size_t)(b * Ln + c * Qn + t) * Hn + h]);
    __syncthreads();

    int qb = t >> 4, pb = t & 15;
    int q0 = qb * 4, p0 = pb * 4;
    float acc[4][4];
    #pragma unroll
    for (int i = 0; i < 4; i++)
        #pragma unroll
        for (int j = 0; j < 4; j++) acc[i][j] = 0.f;
    for (int n = 0; n < Nn; n++) {
        float cq[4], sp[4];
        #pragma unroll
        for (int i = 0; i < 4; i++) cq[i] = Csm[(q0 + i) * 129 + n];
        #pragma unroll
        for (int j = 0; j < 4; j++) sp[j] = Ss[(p0 + j) * 129 + n];
        #pragma unroll
        for (int i = 0; i < 4; i++)
            #pragma unroll
            for (int j = 0; j < 4; j++) acc[i][j] = fmaf(cq[i], sp[j], acc[i][j]);
    }
    #pragma unroll
    for (int i = 0; i < 4; i++) {
        int q = q0 + i;
        float e = Eq[q];
        #pragma unroll
        for (int j = 0; j < 4; j++) {
            int p = p0 + j;
            size_t yi = ((size_t)(b * Ln + c * Qn + q) * Hn + h) * Pn + p;
            g_y[yi] += e * acc[i][j];
        }
    }
}

// ---------------- 8) gated rmsnorm: yg = rmsnorm(y * silu(z)) * gw ----------------
__global__ __launch_bounds__(256) void k_gatenorm(const float* __restrict__ gw) {
    size_t row = blockIdx.x;
    int t = threadIdx.x;
    float v[16];
    float ss = 0.f;
    #pragma unroll
    for (int i = 0; i < 16; i++) {
        int idx = t + i * 256;
        float z = g_proj[row * PROJW + idx];
        float x = g_y[row * DINn + idx] * siluf(z);
        v[i] = x;
        ss += x * x;
    }
    float tot = block_reduce_sum(ss);
    float inv = rsqrtf(tot / (float)DINn + EPSf);
    #pragma unroll
    for (int i = 0; i < 16; i++) {
        int idx = t + i * 256;
        g_yg[row * DINn + idx] = v[i] * inv * gw[idx];
    }
}

// ---------------- launch ----------------
extern "C" void kernel_launch(void* const* d_in, const int* in_sizes, int n_in,
                              void* d_out, int out_size) {
    const float* hs   = (const float*)d_in[0];
    const float* res  = (const float*)d_in[1];
    const float* nw   = (const float*)d_in[2];
    const float* ipw  = (const float*)d_in[3];
    const float* cw   = (const float*)d_in[4];
    const float* cb   = (const float*)d_in[5];
    const float* alog = (const float*)d_in[6];
    const float* dtb  = (const float*)d_in[7];
    const float* dsk  = (const float*)d_in[8];
    const float* gnw  = (const float*)d_in[9];
    const float* opw  = (const float*)d_in[10];
    float* out = (float*)d_out;

    // scratch symbol addresses (for the generic GEMM)
    void *ph, *pproj, *pyg, *pyfb;
    cudaGetSymbolAddress(&ph, g_h);
    cudaGetSymbolAddress(&pproj, g_proj);
    cudaGetSymbolAddress(&pyg, g_yg);
    cudaGetSymbolAddress(&pyfb, g_y);

    // second output (resid). If out holds both tensors, write after out-proj block.
    float* resid_ptr = ((size_t)out_size >= 2ull * BLn * Dn)
                           ? out + (size_t)BLn * Dn
                           : (float*)pyfb;  // fallback scratch if harness only checks out

    const int SMEM_CHUNK = (2 * 64 * 129 + 2 * 64 * 65 + 128) * 4;  // 99840
    const int SMEM_YOFF  = (2 * 64 * 129 + 64) * 4;                  // 66304
    cudaFuncSetAttribute(k_chunk, cudaFuncAttributeMaxDynamicSharedMemorySize, SMEM_CHUNK);
    cudaFuncSetAttribute(k_yoff,  cudaFuncAttributeMaxDynamicSharedMemorySize, SMEM_YOFF);

    // 1) resid + rmsnorm
    k_add_rmsnorm<<<BLn, 256>>>(hs, res, nw, resid_ptr);

    // 2) proj = h @ in_proj_w   [4096 x 8512, K=2048]
    {
        dim3 grid((PROJW + 127) / 128, BLn / 128);
        sgemm128<<<grid, 256>>>((const float*)ph, ipw, (float*)pproj, BLn, PROJW, Dn);
    }

    // 3) conv + silu
    {
        size_t n = (size_t)BLn * CONVD;
        k_conv<<<(unsigned)((n + 255) / 256), 256>>>(cw, cb);
    }

    // 4) dt / a
    k_dt<<<(BLn * Hn + 255) / 256, 256>>>(dtb, alog);

    // 5) chunk kernel
    {
        dim3 grid(NCn, Hn, Bn);
        k_chunk<<<grid, 256, SMEM_CHUNK>>>(dsk);
    }

    // 6) inter-chunk scan
    k_scan<<<Bn * Hn, 256>>>();

    // 7) Y_off
    {
        dim3 grid(NCn, Hn, Bn);
        k_yoff<<<grid, 256, SMEM_YOFF>>>();
    }

    // 8) gated rmsnorm
    k_gatenorm<<<BLn, 256>>>(gnw);

    // 9) out = yg @ out_proj_w   [4096 x 2048, K=4096]
    {
        dim3 grid((Dn + 127) / 128, BLn / 128);
        sgemm128<<<grid, 256>>>((const float*)pyg, opw, out, BLn, Dn, DINn);
    }
}

// round 3
// speedup vs baseline: 2.8109x; 2.8109x over previous
#include <cuda_runtime.h>
#include <cuda_bf16.h>
#include <math.h>
#include <stdint.h>

// ---------------- problem constants ----------------
#define Bn    2
#define Ln    2048
#define Dn    2048
#define DINn  4096
#define Nn    128
#define Hn    64
#define Pn    64
#define Kc    4
#define CONVD 4352            // DIN + 2*G*N
#define Qn    64
#define NCn   32
#define PROJW 8512            // 2*DIN + 2*G*N + H
#define BLn   (Bn*Ln)         // 4096
#define EPSf  1e-5f

// GEMM tiling
#define A_CH  16384           // bytes per A chunk-tile (128 x 64 bf16, swizzled image)
#define B_CH  32768           // bytes per B chunk-tile (256 x 64 bf16, swizzled image)
#define STG   65536           // stage bytes: Ahi+Alo+Bhi(half)+Blo(half) = 4*16KB
#define SMEM_GEMM (1024 + 2*STG + 64)

#define NCH1  32              // in_proj K chunks (2048/64)
#define NT1   34              // in_proj N tiles  (8704/256)
#define NCH2  64              // out_proj K chunks (4096/64)
#define MTil  32              // M tiles (4096/128)

// ---------------- scratch ----------------
__device__ float g_proj[(size_t)BLn*PROJW];
__device__ float g_xbc[(size_t)BLn*CONVD];
__device__ float g_dt[(size_t)BLn*Hn];
__device__ float g_a[(size_t)BLn*Hn];
__device__ float g_acs[(size_t)BLn*Hn];
__device__ float g_csum[(size_t)Bn*Hn*NCn];
__device__ float g_states[(size_t)Bn*Hn*NCn*Pn*Nn];
__device__ float g_statein[(size_t)Bn*Hn*NCn*Pn*Nn];
__device__ float g_y[(size_t)BLn*DINn];

// bf16 split tile buffers (SW128-swizzled SMEM image, chunk-tiled)
__device__ __align__(1024) unsigned char g_Ahi[(size_t)MTil*NCH2*A_CH];
__device__ __align__(1024) unsigned char g_Alo[(size_t)MTil*NCH2*A_CH];
__device__ __align__(1024) unsigned char g_Bhi[(size_t)NT1*NCH1*B_CH];
__device__ __align__(1024) unsigned char g_Blo[(size_t)NT1*NCH1*B_CH];

// ---------------- PTX helpers ----------------
__device__ __forceinline__ uint32_t smem_u32(const void* p) {
    uint32_t a;
    asm("{ .reg .u64 t; cvta.to.shared.u64 t, %1; cvt.u32.u64 %0, t; }" : "=r"(a) : "l"(p));
    return a;
}
__device__ __forceinline__ uint32_t swz128(uint32_t o) { return o ^ ((o >> 3) & 0x70); }

#define MBAR_INIT(a, c) \
    asm volatile("mbarrier.init.shared.b64 [%0], %1;" :: "r"(a), "r"(c) : "memory")
#define MBAR_EXPECT_TX(a, b) \
    asm volatile("mbarrier.arrive.expect_tx.shared.b64 _, [%0], %1;" :: "r"(a), "r"(b) : "memory")
#define MBAR_WAIT(a, ph) do { \
    uint32_t _m = (a); uint32_t _p = (ph); uint32_t _d; \
    asm volatile("{\n\t.reg .pred p;\n\t" \
        "mbarrier.try_wait.parity.acquire.cta.shared::cta.b64 p, [%1], %2;\n\t" \
        "selp.b32 %0, 1, 0, p;\n\t}" : "=r"(_d) : "r"(_m), "r"(_p) : "memory"); \
    if (!_d) { \
        asm volatile("{\n\t.reg .pred P1;\n\t" \
            "WL_%=:\n\t" \
            "mbarrier.try_wait.parity.acquire.cta.shared::cta.b64 P1, [%0], %1, 0x989680;\n\t" \
            "@P1 bra.uni WD_%=;\n\t" \
            "bra.uni WL_%=;\n\t" \
            "WD_%=:\n\t}" :: "r"(_m), "r"(_p) : "memory"); \
    } \
} while (0)

#define BULK_LD(sa, gp, bytes, mb) \
    asm volatile("cp.async.bulk.shared::cluster.global.mbarrier::complete_tx::bytes [%0], [%1], %2, [%3];" \
        :: "r"(sa), "l"(gp), "r"(bytes), "r"(mb) : "memory")

#define LDSMX4(r, addr) \
    asm volatile("ldmatrix.sync.aligned.m8n8.x4.shared.b16 {%0,%1,%2,%3}, [%4];" \
        : "=r"((r)[0]), "=r"((r)[1]), "=r"((r)[2]), "=r"((r)[3]) : "r"(addr))

#define MMA_BF16(d, a, b0, b1) \
    asm volatile("mma.sync.aligned.m16n8k16.row.col.f32.bf16.bf16.f32 " \
        "{%0,%1,%2,%3}, {%4,%5,%6,%7}, {%8,%9}, {%0,%1,%2,%3};" \
        : "+f"((d)[0]), "+f"((d)[1]), "+f"((d)[2]), "+f"((d)[3]) \
        : "r"((a)[0]), "r"((a)[1]), "r"((a)[2]), "r"((a)[3]), "r"(b0), "r"(b1))

// ---------------- misc helpers ----------------
__device__ __forceinline__ float block_reduce_sum(float v) {
    __shared__ float red[32];
    int lane = threadIdx.x & 31, wid = threadIdx.x >> 5;
    #pragma unroll
    for (int o = 16; o; o >>= 1) v += __shfl_down_sync(0xffffffffu, v, o);
    if (lane == 0) red[wid] = v;
    __syncthreads();
    v = (threadIdx.x < (blockDim.x >> 5)) ? red[threadIdx.x] : 0.f;
    if (wid == 0) {
        #pragma unroll
        for (int o = 16; o; o >>= 1) v += __shfl_down_sync(0xffffffffu, v, o);
        if (lane == 0) red[0] = v;
    }
    __syncthreads();
    return red[0];
}
__device__ __forceinline__ float siluf(float x) { return x / (1.f + expf(-x)); }

__device__ __forceinline__ void split2(float x0, float x1, uint32_t& uhi, uint32_t& ulo) {
    __nv_bfloat16 h0 = __float2bfloat16(x0);
    __nv_bfloat16 h1 = __float2bfloat16(x1);
    __nv_bfloat16 l0 = __float2bfloat16(x0 - __bfloat162float(h0));
    __nv_bfloat16 l1 = __float2bfloat16(x1 - __bfloat162float(h1));
    uhi = ((uint32_t)__bfloat16_as_ushort(h1) << 16) | __bfloat16_as_ushort(h0);
    ulo = ((uint32_t)__bfloat16_as_ushort(l1) << 16) | __bfloat16_as_ushort(l0);
}

// ---------------- 1) resid + rmsnorm -> bf16 split A tiles (K=2048, nch=32) ----------------
__global__ __launch_bounds__(256) void k_add_rmsnorm_split(
    const float* __restrict__ hs, const float* __restrict__ res,
    const float* __restrict__ w, float* __restrict__ resid_out,
    unsigned char* __restrict__ Ahi, unsigned char* __restrict__ Alo) {
    size_t row = blockIdx.x;
    int t = threadIdx.x;
    const float4* ph = (const float4*)(hs + row * Dn);
    const float4* pr = (const float4*)(res + row * Dn);
    float4* po = (float4*)(resid_out + row * Dn);
    float v[8];
    float ss = 0.f;
    #pragma unroll
    for (int i = 0; i < 2; i++) {
        float4 a = ph[t * 2 + i], b = pr[t * 2 + i];
        float4 x = make_float4(a.x + b.x, a.y + b.y, a.z + b.z, a.w + b.w);
        po[t * 2 + i] = x;
        v[i * 4 + 0] = x.x; v[i * 4 + 1] = x.y; v[i * 4 + 2] = x.z; v[i * 4 + 3] = x.w;
        ss += x.x * x.x + x.y * x.y + x.z * x.z + x.w * x.w;
    }
    float tot = block_reduce_sum(ss);
    float inv = rsqrtf(tot / (float)Dn + EPSf);
    int mt = (int)(row >> 7), r = (int)(row & 127);
    size_t tb = (size_t)mt * NCH1 * A_CH;
    #pragma unroll
    for (int j = 0; j < 4; j++) {
        int k = t * 8 + j * 2;
        float x0 = v[j * 2] * inv * w[k];
        float x1 = v[j * 2 + 1] * inv * w[k + 1];
        uint32_t uhi, ulo;
        split2(x0, x1, uhi, ulo);
        int kc = k >> 6, c = k & 63;
        size_t off = tb + (size_t)kc * A_CH + swz128((uint32_t)(r * 128 + c * 2));
        *(uint32_t*)(Ahi + off) = uhi;
        *(uint32_t*)(Alo + off) = ulo;
    }
}

// ---------------- weight transpose + split: W[K x N] -> B tiles [nt][kc][256][64] ----------------
__global__ __launch_bounds__(256) void k_splitB(
    const float* __restrict__ W, unsigned char* __restrict__ Bhi,
    unsigned char* __restrict__ Blo, int Nreal, int nch) {
    __shared__ float tile[64][33];
    int kb = blockIdx.y * 64;
    int n0 = blockIdx.x * 32;
    int t = threadIdx.x;
    int tx = t & 31, ty = t >> 5;
    #pragma unroll
    for (int i = 0; i < 8; i++) {
        int k = ty + i * 8;
        tile[k][tx] = W[(size_t)(kb + k) * Nreal + n0 + tx];
    }
    __syncthreads();
    int kc = kb >> 6;
    #pragma unroll
    for (int j = 0; j < 4; j++) {
        int nl = ty * 4 + j;
        int n = n0 + nl;
        float x0 = tile[tx * 2][nl];
        float x1 = tile[tx * 2 + 1][nl];
        uint32_t uhi, ulo;
        split2(x0, x1, uhi, ulo);
        int nt = n >> 8, r = n & 255;
        size_t base = ((size_t)(nt * nch + kc)) * B_CH;
        size_t off = base + swz128((uint32_t)(r * 128 + tx * 4));
        *(uint32_t*)(Bhi + off) = uhi;
        *(uint32_t*)(Blo + off) = ulo;
    }
}

// ---------------- bf16x3 GEMM via mma.sync (HMMA): C = split(A) @ split(B)^T ----------------
// Block tile 128(M) x 128(N), BK=64, 256 threads, 2-stage bulk-copy pipeline.
__global__ __launch_bounds__(256) void gemm_mma_bf16x3(
    const unsigned char* __restrict__ Ahi, const unsigned char* __restrict__ Alo,
    const unsigned char* __restrict__ Bhi, const unsigned char* __restrict__ Blo,
    float* __restrict__ C, int Nreal, int nch) {
    extern __shared__ unsigned char smg[];
    uint32_t sb = (smem_u32(smg) + 1023) & ~1023u;
    uint32_t ctrl = sb + 2 * STG;
    int t = threadIdx.x, lane = t & 31, wid = t >> 5;
    int bx = blockIdx.x, by = blockIdx.y;

    if (t == 0) { MBAR_INIT(ctrl + 0, 1); MBAR_INIT(ctrl + 8, 1); }
    __syncthreads();

    const unsigned char* Ah = Ahi + (size_t)by * nch * A_CH;
    const unsigned char* Al = Alo + (size_t)by * nch * A_CH;
    size_t bbase = (size_t)(bx >> 1) * nch * B_CH + (size_t)(bx & 1) * 16384;
    const unsigned char* Bh = Bhi + bbase;
    const unsigned char* Bl = Blo + bbase;

    int wm = wid & 1, wn = wid >> 1;          // warp tile: 64(M) x 32(N)
    int rowA = wm * 64 + (lane & 7) + ((lane >> 3) & 1) * 8;
    int colA = ((lane >> 4) & 1) * 16;
    int rowB = wn * 32 + (lane & 7) + ((lane >> 4) & 1) * 8;
    int colB = ((lane >> 3) & 1) * 16;

    float acc[4][4][4];
    #pragma unroll
    for (int i = 0; i < 4; i++)
        #pragma unroll
        for (int j = 0; j < 4; j++)
            #pragma unroll
            for (int q = 0; q < 4; q++) acc[i][j][q] = 0.f;

    if (t == 0) {
        MBAR_EXPECT_TX(ctrl + 0, STG);
        BULK_LD(sb + 0,     Ah, 16384, ctrl + 0);
        BULK_LD(sb + 16384, Al, 16384, ctrl + 0);
        BULK_LD(sb + 32768, Bh, 16384, ctrl + 0);
        BULK_LD(sb + 49152, Bl, 16384, ctrl + 0);
    }
    int ph0 = 0, ph1 = 0;
    for (int kc = 0; kc < nch; kc++) {
        int buf = kc & 1;
        if (t == 0 && kc + 1 < nch) {
            uint32_t s = sb + (buf ^ 1) * STG;
            uint32_t mb = ctrl + (buf ^ 1) * 8;
            MBAR_EXPECT_TX(mb, STG);
            BULK_LD(s + 0,     Ah + (size_t)(kc + 1) * A_CH, 16384, mb);
            BULK_LD(s + 16384, Al + (size_t)(kc + 1) * A_CH, 16384, mb);
            BULK_LD(s + 32768, Bh + (size_t)(kc + 1) * B_CH, 16384, mb);
            BULK_LD(s + 49152, Bl + (size_t)(kc + 1) * B_CH, 16384, mb);
        }
        if (buf == 0) { MBAR_WAIT(ctrl + 0, ph0); ph0 ^= 1; }
        else          { MBAR_WAIT(ctrl + 8, ph1); ph1 ^= 1; }
        uint32_t s = sb + buf * STG;
        uint32_t sAh = s, sAl = s + 16384, sBh = s + 32768, sBl = s + 49152;
        #pragma unroll
        for (int k = 0; k < 4; k++) {
            uint32_t bh[2][4], bl[2][4];
            #pragma unroll
            for (int ib = 0; ib < 2; ib++) {
                uint32_t off = swz128((uint32_t)((rowB + ib * 16) * 128 + k * 32 + colB));
                LDSMX4(bh[ib], sBh + off);
                LDSMX4(bl[ib], sBl + off);
            }
            #pragma unroll
            for (int im = 0; im < 4; im++) {
                uint32_t ah[4], al[4];
                uint32_t off = swz128((uint32_t)((rowA + im * 16) * 128 + k * 32 + colA));
                LDSMX4(ah, sAh + off);
                LDSMX4(al, sAl + off);
                // pass 1: Ahi*Bhi
                #pragma unroll
                for (int ib = 0; ib < 2; ib++)
                    #pragma unroll
                    for (int hf = 0; hf < 2; hf++)
                        MMA_BF16(acc[im][ib * 2 + hf], ah, bh[ib][2 * hf], bh[ib][2 * hf + 1]);
                // pass 2: Ahi*Blo
                #pragma unroll
                for (int ib = 0; ib < 2; ib++)
                    #pragma unroll
                    for (int hf = 0; hf < 2; hf++)
                        MMA_BF16(acc[im][ib * 2 + hf], ah, bl[ib][2 * hf], bl[ib][2 * hf + 1]);
                // pass 3: Alo*Bhi
                #pragma unroll
                for (int ib = 0; ib < 2; ib++)
                    #pragma unroll
                    for (int hf = 0; hf < 2; hf++)
                        MMA_BF16(acc[im][ib * 2 + hf], al, bh[ib][2 * hf], bh[ib][2 * hf + 1]);
            }
        }
        __syncthreads();
    }

    // epilogue: direct fp32 stores (float2 per fragment row)
    int mBase = by * 128 + wm * 64;
    int nBase = bx * 128 + wn * 32;
    #pragma unroll
    for (int im = 0; im < 4; im++) {
        #pragma unroll
        for (int in = 0; in < 4; in++) {
            int r = mBase + im * 16 + (lane >> 2);
            int c = nBase + in * 8 + (lane & 3) * 2;
            if (c < Nreal) {
                float2 v0 = make_float2(acc[im][in][0], acc[im][in][1]);
                float2 v1 = make_float2(acc[im][in][2], acc[im][in][3]);
                *(float2*)(C + (size_t)r * Nreal + c) = v0;
                *(float2*)(C + (size_t)(r + 8) * Nreal + c) = v1;
            }
        }
    }
}

// ---------------- 3) causal depthwise conv (K=4) + bias + silu ----------------
__global__ __launch_bounds__(256) void k_conv(
    const float* __restrict__ cw, const float* __restrict__ cb) {
    size_t idx = (size_t)blockIdx.x * 256 + threadIdx.x;
    if (idx >= (size_t)BLn * CONVD) return;
    int c = (int)(idx % CONVD);
    int bl = (int)(idx / CONVD);
    int l = bl % Ln;
    int b = bl / Ln;
    float acc = cb[c];
    #pragma unroll
    for (int k = 0; k < Kc; k++) {
        int ls = l - (Kc - 1) + k;
        if (ls >= 0)
            acc = fmaf(cw[c * Kc + k],
                       g_proj[((size_t)(b * Ln + ls)) * PROJW + DINn + c], acc);
    }
    g_xbc[idx] = siluf(acc);
}

// ---------------- 4) dt / a ----------------
__global__ __launch_bounds__(256) void k_dt(
    const float* __restrict__ dtb, const float* __restrict__ alog) {
    int idx = blockIdx.x * 256 + threadIdx.x;
    if (idx >= BLn * Hn) return;
    int h = idx & (Hn - 1);
    int bl = idx / Hn;
    float x = g_proj[(size_t)bl * PROJW + (DINn + CONVD) + h] + dtb[h];
    float sp = (x > 20.f) ? x : log1pf(expf(x));
    g_dt[idx] = sp;
    g_a[idx] = -expf(alog[h]) * sp;
}

// ---------------- 5) per-chunk: cumsum, Y_diag + D*xs, local states ----------------
__global__ __launch_bounds__(256) void k_chunk(const float* __restrict__ dskip) {
    extern __shared__ float sm[];
    float* Bsm = sm;
    float* Csm = Bsm + 64 * 129;
    float* Xd  = Csm + 64 * 129;
    float* Ms  = Xd + 64 * 65;
    float* Acs = Ms + 64 * 65;
    float* Dec = Acs + 64;

    int c = blockIdx.x, h = blockIdx.y, b = blockIdx.z;
    int t = threadIdx.x;
    size_t rowbase = ((size_t)(b * Ln + c * Qn)) * CONVD;

    for (int i = t; i < Qn * Nn; i += 256) {
        int s = i >> 7, n = i & 127;
        size_t g = rowbase + (size_t)s * CONVD + DINn;
        Bsm[s * 129 + n] = g_xbc[g + n];
        Csm[s * 129 + n] = g_xbc[g + Nn + n];
    }
    if (t < Qn) Acs[t] = g_a[(size_t)(b * Ln + c * Qn + t) * Hn + h];
    __syncthreads();
    if (t == 0) {
        float r = 0.f;
        for (int i = 0; i < Qn; i++) { r += Acs[i]; Acs[i] = r; }
    }
    __syncthreads();
    if (t < Qn) {
        float aq = Acs[t];
        Dec[t] = expf(Acs[Qn - 1] - aq);
        g_acs[(size_t)(b * Ln + c * Qn + t) * Hn + h] = aq;
        if (t == Qn - 1) g_csum[(size_t)(b * Hn + h) * NCn + c] = aq;
    }
    for (int i = t; i < Qn * Pn; i += 256) {
        int s = i >> 6, p = i & 63;
        float xs = g_xbc[rowbase + (size_t)s * CONVD + h * Pn + p];
        Xd[s * 65 + p] = xs * g_dt[(size_t)(b * Ln + c * Qn + s) * Hn + h];
    }
    __syncthreads();

    {
        int qb = t >> 4, sbq = t & 15;
        int q0 = qb * 4, s0 = sbq * 4;
        float m4[4][4];
        #pragma unroll
        for (int i = 0; i < 4; i++)
            #pragma unroll
            for (int j = 0; j < 4; j++) m4[i][j] = 0.f;
        if (s0 <= q0 + 3) {
            for (int n = 0; n < Nn; n++) {
                float cq[4], bs[4];
                #pragma unroll
                for (int i = 0; i < 4; i++) cq[i] = Csm[(q0 + i) * 129 + n];
                #pragma unroll
                for (int j = 0; j < 4; j++) bs[j] = Bsm[(s0 + j) * 129 + n];
                #pragma unroll
                for (int i = 0; i < 4; i++)
                    #pragma unroll
                    for (int j = 0; j < 4; j++) m4[i][j] = fmaf(cq[i], bs[j], m4[i][j]);
            }
        }
        #pragma unroll
        for (int i = 0; i < 4; i++)
            #pragma unroll
            for (int j = 0; j < 4; j++) {
                int q = q0 + i, s = s0 + j;
                Ms[q * 65 + s] = (s <= q) ? m4[i][j] * expf(Acs[q] - Acs[s]) : 0.f;
            }
    }
    __syncthreads();

    {
        int qb = t >> 4, pb = t & 15;
        int q0 = qb * 4, p0 = pb * 4;
        float y4[4][4];
        #pragma unroll
        for (int i = 0; i < 4; i++)
            #pragma unroll
            for (int j = 0; j < 4; j++) y4[i][j] = 0.f;
        int smax = q0 + 3;
        for (int s = 0; s <= smax; s++) {
            float mv[4], xv[4];
            #pragma unroll
            for (int i = 0; i < 4; i++) mv[i] = Ms[(q0 + i) * 65 + s];
            #pragma unroll
            for (int j = 0; j < 4; j++) xv[j] = Xd[s * 65 + p0 + j];
            #pragma unroll
            for (int i = 0; i < 4; i++)
                #pragma unroll
                for (int j = 0; j < 4; j++) y4[i][j] = fmaf(mv[i], xv[j], y4[i][j]);
        }
        float dsk = dskip[h];
        #pragma unroll
        for (int i = 0; i < 4; i++) {
            int q = q0 + i;
            #pragma unroll
            for (int j = 0; j < 4; j++) {
                int p = p0 + j;
                float xs = g_xbc[rowbase + (size_t)q * CONVD + h * Pn + p];
                g_y[((size_t)(b * Ln + c * Qn + q) * Hn + h) * Pn + p] =
                    y4[i][j] + dsk * xs;
            }
        }
    }

    {
        int pb = t >> 4, nb2 = t & 15;
        int p0 = pb * 4, n0 = nb2 * 8;
        float st[4][8];
        #pragma unroll
        for (int i = 0; i < 4; i++)
            #pragma unroll
            for (int j = 0; j < 8; j++) st[i][j] = 0.f;
        for (int q = 0; q < Qn; q++) {
            float d = Dec[q];
            float xv[4], bv[8];
            #pragma unroll
            for (int i = 0; i < 4; i++) xv[i] = Xd[q * 65 + p0 + i] * d;
            #pragma unroll
            for (int j = 0; j < 8; j++) bv[j] = Bsm[q * 129 + n0 + j];
            #pragma unroll
            for (int i = 0; i < 4; i++)
                #pragma unroll
                for (int j = 0; j < 8; j++) st[i][j] = fmaf(xv[i], bv[j], st[i][j]);
        }
        size_t base = ((size_t)(b * Hn + h) * NCn + c) * (Pn * Nn);
        #pragma unroll
        for (int i = 0; i < 4; i++)
            #pragma unroll
            for (int j = 0; j < 8; j++)
                g_states[base + (size_t)(p0 + i) * Nn + n0 + j] = st[i][j];
    }
}

// ---------------- 6) chunk-level scan ----------------
__global__ __launch_bounds__(256) void k_scan() {
    int bh = blockIdx.x;
    int t = threadIdx.x;
    float S[32];
    #pragma unroll
    for (int k = 0; k < 32; k++) S[k] = 0.f;
    for (int c = 0; c < NCn; c++) {
        size_t base = ((size_t)bh * NCn + c) * (Pn * Nn);
        #pragma unroll
        for (int k = 0; k < 32; k++) g_statein[base + t + k * 256] = S[k];
        float f = expf(g_csum[(size_t)bh * NCn + c]);
        #pragma unroll
        for (int k = 0; k < 32; k++)
            S[k] = fmaf(f, S[k], g_states[base + t + k * 256]);
    }
}

// ---------------- 7) Y_off ----------------
__global__ __launch_bounds__(256) void k_yoff() {
    extern __shared__ float sm[];
    float* Ss  = sm;
    float* Csm = Ss + 64 * 129;
    float* Eq  = Csm + 64 * 129;

    int c = blockIdx.x, h = blockIdx.y, b = blockIdx.z;
    int t = threadIdx.x;
    size_t rowbase = ((size_t)(b * Ln + c * Qn)) * CONVD;
    size_t sbase = ((size_t)(b * Hn + h) * NCn + c) * (Pn * Nn);

    for (int i = t; i < Pn * Nn; i += 256) {
        int p = i >> 7, n = i & 127;
        Ss[p * 129 + n] = g_statein[sbase + i];
    }
    for (int i = t; i < Qn * Nn; i += 256) {
        int q = i >> 7, n = i & 127;
        Csm[q * 129 + n] = g_xbc[rowbase + (size_t)q * CONVD + DINn + Nn + n];
    }
    if (t < Qn)
        Eq[t] = expf(g_acs[(size_t)(b * Ln + c * Qn + t) * Hn + h]);
    __syncthreads();

    int qb = t >> 4, pb = t & 15;
    int q0 = qb * 4, p0 = pb * 4;
    float acc[4][4];
    #pragma unroll
    for (int i = 0; i < 4; i++)
        #pragma unroll
        for (int j = 0; j < 4; j++) acc[i][j] = 0.f;
    for (int n = 0; n < Nn; n++) {
        float cq[4], sp[4];
        #pragma unroll
        for (int i = 0; i < 4; i++) cq[i] = Csm[(q0 + i) * 129 + n];
        #pragma unroll
        for (int j = 0; j < 4; j++) sp[j] = Ss[(p0 + j) * 129 + n];
        #pragma unroll
        for (int i = 0; i < 4; i++)
            #pragma unroll
            for (int j = 0; j < 4; j++) acc[i][j] = fmaf(cq[i], sp[j], acc[i][j]);
    }
    #pragma unroll
    for (int i = 0; i < 4; i++) {
        int q = q0 + i;
        float e = Eq[q];
        #pragma unroll
        for (int j = 0; j < 4; j++) {
            int p = p0 + j;
            size_t yi = ((size_t)(b * Ln + c * Qn + q) * Hn + h) * Pn + p;
            g_y[yi] += e * acc[i][j];
        }
    }
}

// ---------------- 8) gated rmsnorm -> bf16 split A tiles (K=4096, nch=64) ----------------
__global__ __launch_bounds__(256) void k_gatenorm_split(
    const float* __restrict__ gw,
    unsigned char* __restrict__ Ahi, unsigned char* __restrict__ Alo) {
    size_t row = blockIdx.x;
    int t = threadIdx.x;
    const float4* py = (const float4*)(g_y + row * DINn);
    const float4* pz = (const float4*)(g_proj + row * PROJW);
    float v[16];
    float ss = 0.f;
    #pragma unroll
    for (int i = 0; i < 4; i++) {
        float4 y4 = py[t * 4 + i];
        float4 z4 = pz[t * 4 + i];
        float x0 = y4.x * siluf(z4.x);
        float x1 = y4.y * siluf(z4.y);
        float x2 = y4.z * siluf(z4.z);
        float x3 = y4.w * siluf(z4.w);
        v[i * 4 + 0] = x0; v[i * 4 + 1] = x1; v[i * 4 + 2] = x2; v[i * 4 + 3] = x3;
        ss += x0 * x0 + x1 * x1 + x2 * x2 + x3 * x3;
    }
    float tot = block_reduce_sum(ss);
    float inv = rsqrtf(tot / (float)DINn + EPSf);
    int mt = (int)(row >> 7), r = (int)(row & 127);
    size_t tb = (size_t)mt * NCH2 * A_CH;
    #pragma unroll
    for (int j = 0; j < 8; j++) {
        int k = t * 16 + j * 2;
        float x0 = v[j * 2] * inv * gw[k];
        float x1 = v[j * 2 + 1] * inv * gw[k + 1];
        uint32_t uhi, ulo;
        split2(x0, x1, uhi, ulo);
        int kc = k >> 6, cc = k & 63;
        size_t off = tb + (size_t)kc * A_CH + swz128((uint32_t)(r * 128 + cc * 2));
        *(uint32_t*)(Ahi + off) = uhi;
        *(uint32_t*)(Alo + off) = ulo;
    }
}

// ---------------- launch ----------------
extern "C" void kernel_launch(void* const* d_in, const int* in_sizes, int n_in,
                              void* d_out, int out_size) {
    const float* hs   = (const float*)d_in[0];
    const float* res  = (const float*)d_in[1];
    const float* nw   = (const float*)d_in[2];
    const float* ipw  = (const float*)d_in[3];
    const float* cw   = (const float*)d_in[4];
    const float* cb   = (const float*)d_in[5];
    const float* alog = (const float*)d_in[6];
    const float* dtb  = (const float*)d_in[7];
    const float* dsk  = (const float*)d_in[8];
    const float* gnw  = (const float*)d_in[9];
    const float* opw  = (const float*)d_in[10];
    float* out = (float*)d_out;

    void *pproj, *pAhi, *pAlo, *pBhi, *pBlo, *pyfb;
    cudaGetSymbolAddress(&pproj, g_proj);
    cudaGetSymbolAddress(&pAhi, g_Ahi);
    cudaGetSymbolAddress(&pAlo, g_Alo);
    cudaGetSymbolAddress(&pBhi, g_Bhi);
    cudaGetSymbolAddress(&pBlo, g_Blo);
    cudaGetSymbolAddress(&pyfb, g_y);

    float* resid_ptr = ((size_t)out_size >= 2ull * BLn * Dn)
                           ? out + (size_t)BLn * Dn
                           : (float*)pyfb;

    const int SMEM_CHUNK = (2 * 64 * 129 + 2 * 64 * 65 + 128) * 4;
    const int SMEM_YOFF  = (2 * 64 * 129 + 64) * 4;
    cudaFuncSetAttribute(k_chunk, cudaFuncAttributeMaxDynamicSharedMemorySize, SMEM_CHUNK);
    cudaFuncSetAttribute(k_yoff,  cudaFuncAttributeMaxDynamicSharedMemorySize, SMEM_YOFF);
    cudaFuncSetAttribute(gemm_mma_bf16x3, cudaFuncAttributeMaxDynamicSharedMemorySize, SMEM_GEMM);

    // 1) resid + rmsnorm -> A tiles (bf16 hi/lo)
    k_add_rmsnorm_split<<<BLn, 256>>>(hs, res, nw, resid_ptr,
                                      (unsigned char*)pAhi, (unsigned char*)pAlo);

    // 2a) split+transpose in_proj_w -> B tiles
    {
        dim3 grid(PROJW / 32, Dn / 64);
        k_splitB<<<grid, 256>>>(ipw, (unsigned char*)pBhi, (unsigned char*)pBlo,
                                PROJW, NCH1);
    }
    // 2b) proj = h @ in_proj_w  (HMMA bf16x3)
    {
        dim3 grid(68, MTil);   // 68*128 = 8704 padded N
        gemm_mma_bf16x3<<<grid, 256, SMEM_GEMM>>>(
            (const unsigned char*)pAhi, (const unsigned char*)pAlo,
            (const unsigned char*)pBhi, (const unsigned char*)pBlo,
            (float*)pproj, PROJW, NCH1);
    }

    // 3) conv + silu
    {
        size_t n = (size_t)BLn * CONVD;
        k_conv<<<(unsigned)((n + 255) / 256), 256>>>(cw, cb);
    }

    // 4) dt / a
    k_dt<<<(BLn * Hn + 255) / 256, 256>>>(dtb, alog);

    // 5) chunk kernel
    {
        dim3 grid(NCn, Hn, Bn);
        k_chunk<<<grid, 256, SMEM_CHUNK>>>(dsk);
    }

    // 6) inter-chunk scan
    k_scan<<<Bn * Hn, 256>>>();

    // 7) Y_off
    {
        dim3 grid(NCn, Hn, Bn);
        k_yoff<<<grid, 256, SMEM_YOFF>>>();
    }

    // 8) gated rmsnorm -> A tiles (bf16 hi/lo, K=4096)
    k_gatenorm_split<<<BLn, 256>>>(gnw, (unsigned char*)pAhi, (unsigned char*)pAlo);

    // 9a) split+transpose out_proj_w -> B tiles
    {
        dim3 grid(Dn / 32, DINn / 64);
        k_splitB<<<grid, 256>>>(opw, (unsigned char*)pBhi, (unsigned char*)pBlo,
                                Dn, NCH2);
    }
    // 9b) out = yg @ out_proj_w
    {
        dim3 grid(16, MTil);   // 16*128 = 2048
        gemm_mma_bf16x3<<<grid, 256, SMEM_GEMM>>>(
            (const unsigned char*)pAhi, (const unsigned char*)pAlo,
            (const unsigned char*)pBhi, (const unsigned char*)pBlo,
            out, Dn, NCH2);
    }
}

// round 4
// speedup vs baseline: 2.9167x; 1.0376x over previous
#include <cuda_runtime.h>
#include <cuda_bf16.h>
#include <math.h>
#include <stdint.h>

// ---------------- problem constants ----------------
#define Bn    2
#define Ln    2048
#define Dn    2048
#define DINn  4096
#define Nn    128
#define Hn    64
#define Pn    64
#define Kc    4
#define CONVD 4352            // DIN + 2*G*N
#define Qn    64
#define NCn   32
#define PROJW 8512            // 2*DIN + 2*G*N + H
#define BLn   (Bn*Ln)         // 4096
#define EPSf  1e-5f

// GEMM tiling: 128(M) x 256(N) block tile, BK=64, 512 threads
#define A_CH  16384           // bytes per A chunk-tile (128 x 64 bf16, swizzled image)
#define B_CH  32768           // bytes per B chunk-tile (256 x 64 bf16, swizzled image)
#define STG   98304           // stage bytes: Ahi+Alo+Bhi+Blo = 16K+16K+32K+32K
#define SMEM_GEMM (1024 + 2*STG + 64)

#define NCH1  32              // in_proj K chunks (2048/64)
#define NT1   34              // in_proj N tiles  (8704/256)
#define NCH2  64              // out_proj K chunks (4096/64)
#define MTil  32              // M tiles (4096/128)

// ---------------- scratch ----------------
__device__ float g_proj[(size_t)BLn*PROJW];
__device__ float g_xbc[(size_t)BLn*CONVD];
__device__ float g_dt[(size_t)BLn*Hn];
__device__ float g_a[(size_t)BLn*Hn];
__device__ float g_acs[(size_t)BLn*Hn];
__device__ float g_csum[(size_t)Bn*Hn*NCn];
__device__ float g_states[(size_t)Bn*Hn*NCn*Pn*Nn];
__device__ float g_statein[(size_t)Bn*Hn*NCn*Pn*Nn];
__device__ float g_y[(size_t)BLn*DINn];

// bf16 split tile buffers (SW128-swizzled SMEM image, chunk-tiled)
__device__ __align__(1024) unsigned char g_Ahi[(size_t)MTil*NCH2*A_CH];
__device__ __align__(1024) unsigned char g_Alo[(size_t)MTil*NCH2*A_CH];
__device__ __align__(1024) unsigned char g_Bhi[(size_t)NT1*NCH1*B_CH];
__device__ __align__(1024) unsigned char g_Blo[(size_t)NT1*NCH1*B_CH];

// ---------------- PTX helpers ----------------
__device__ __forceinline__ uint32_t smem_u32(const void* p) {
    uint32_t a;
    asm("{ .reg .u64 t; cvta.to.shared.u64 t, %1; cvt.u32.u64 %0, t; }" : "=r"(a) : "l"(p));
    return a;
}
__device__ __forceinline__ uint32_t swz128(uint32_t o) { return o ^ ((o >> 3) & 0x70); }

#define MBAR_INIT(a, c) \
    asm volatile("mbarrier.init.shared.b64 [%0], %1;" :: "r"(a), "r"(c) : "memory")
#define MBAR_EXPECT_TX(a, b) \
    asm volatile("mbarrier.arrive.expect_tx.shared.b64 _, [%0], %1;" :: "r"(a), "r"(b) : "memory")
#define MBAR_WAIT(a, ph) do { \
    uint32_t _m = (a); uint32_t _p = (ph); uint32_t _d; \
    asm volatile("{\n\t.reg .pred p;\n\t" \
        "mbarrier.try_wait.parity.acquire.cta.shared::cta.b64 p, [%1], %2;\n\t" \
        "selp.b32 %0, 1, 0, p;\n\t}" : "=r"(_d) : "r"(_m), "r"(_p) : "memory"); \
    if (!_d) { \
        asm volatile("{\n\t.reg .pred P1;\n\t" \
            "WL_%=:\n\t" \
            "mbarrier.try_wait.parity.acquire.cta.shared::cta.b64 P1, [%0], %1, 0x989680;\n\t" \
            "@P1 bra.uni WD_%=;\n\t" \
            "bra.uni WL_%=;\n\t" \
            "WD_%=:\n\t}" :: "r"(_m), "r"(_p) : "memory"); \
    } \
} while (0)

#define BULK_LD(sa, gp, bytes, mb) \
    asm volatile("cp.async.bulk.shared::cluster.global.mbarrier::complete_tx::bytes [%0], [%1], %2, [%3];" \
        :: "r"(sa), "l"(gp), "r"(bytes), "r"(mb) : "memory")

#define LDSMX4(r, addr) \
    asm volatile("ldmatrix.sync.aligned.m8n8.x4.shared.b16 {%0,%1,%2,%3}, [%4];" \
        : "=r"((r)[0]), "=r"((r)[1]), "=r"((r)[2]), "=r"((r)[3]) : "r"(addr))

#define MMA_BF16(d, a, b0, b1) \
    asm volatile("mma.sync.aligned.m16n8k16.row.col.f32.bf16.bf16.f32 " \
        "{%0,%1,%2,%3}, {%4,%5,%6,%7}, {%8,%9}, {%0,%1,%2,%3};" \
        : "+f"((d)[0]), "+f"((d)[1]), "+f"((d)[2]), "+f"((d)[3]) \
        : "r"((a)[0]), "r"((a)[1]), "r"((a)[2]), "r"((a)[3]), "r"(b0), "r"(b1))

// ---------------- misc helpers ----------------
__device__ __forceinline__ float block_reduce_sum(float v) {
    __shared__ float red[32];
    int lane = threadIdx.x & 31, wid = threadIdx.x >> 5;
    #pragma unroll
    for (int o = 16; o; o >>= 1) v += __shfl_down_sync(0xffffffffu, v, o);
    if (lane == 0) red[wid] = v;
    __syncthreads();
    v = (threadIdx.x < (blockDim.x >> 5)) ? red[threadIdx.x] : 0.f;
    if (wid == 0) {
        #pragma unroll
        for (int o = 16; o; o >>= 1) v += __shfl_down_sync(0xffffffffu, v, o);
        if (lane == 0) red[0] = v;
    }
    __syncthreads();
    return red[0];
}
__device__ __forceinline__ float siluf(float x) { return x / (1.f + expf(-x)); }

__device__ __forceinline__ void split2(float x0, float x1, uint32_t& uhi, uint32_t& ulo) {
    __nv_bfloat16 h0 = __float2bfloat16(x0);
    __nv_bfloat16 h1 = __float2bfloat16(x1);
    __nv_bfloat16 l0 = __float2bfloat16(x0 - __bfloat162float(h0));
    __nv_bfloat16 l1 = __float2bfloat16(x1 - __bfloat162float(h1));
    uhi = ((uint32_t)__bfloat16_as_ushort(h1) << 16) | __bfloat16_as_ushort(h0);
    ulo = ((uint32_t)__bfloat16_as_ushort(l1) << 16) | __bfloat16_as_ushort(l0);
}

// ---------------- 1) resid + rmsnorm -> bf16 split A tiles (K=2048, nch=32) ----------------
__global__ __launch_bounds__(256) void k_add_rmsnorm_split(
    const float* __restrict__ hs, const float* __restrict__ res,
    const float* __restrict__ w, float* __restrict__ resid_out,
    unsigned char* __restrict__ Ahi, unsigned char* __restrict__ Alo) {
    size_t row = blockIdx.x;
    int t = threadIdx.x;
    const float4* ph = (const float4*)(hs + row * Dn);
    const float4* pr = (const float4*)(res + row * Dn);
    float4* po = (float4*)(resid_out + row * Dn);
    float v[8];
    float ss = 0.f;
    #pragma unroll
    for (int i = 0; i < 2; i++) {
        float4 a = ph[t * 2 + i], b = pr[t * 2 + i];
        float4 x = make_float4(a.x + b.x, a.y + b.y, a.z + b.z, a.w + b.w);
        po[t * 2 + i] = x;
        v[i * 4 + 0] = x.x; v[i * 4 + 1] = x.y; v[i * 4 + 2] = x.z; v[i * 4 + 3] = x.w;
        ss += x.x * x.x + x.y * x.y + x.z * x.z + x.w * x.w;
    }
    float tot = block_reduce_sum(ss);
    float inv = rsqrtf(tot / (float)Dn + EPSf);
    int mt = (int)(row >> 7), r = (int)(row & 127);
    size_t tb = (size_t)mt * NCH1 * A_CH;
    #pragma unroll
    for (int j = 0; j < 4; j++) {
        int k = t * 8 + j * 2;
        float x0 = v[j * 2] * inv * w[k];
        float x1 = v[j * 2 + 1] * inv * w[k + 1];
        uint32_t uhi, ulo;
        split2(x0, x1, uhi, ulo);
        int kc = k >> 6, c = k & 63;
        size_t off = tb + (size_t)kc * A_CH + swz128((uint32_t)(r * 128 + c * 2));
        *(uint32_t*)(Ahi + off) = uhi;
        *(uint32_t*)(Alo + off) = ulo;
    }
}

// ---------------- weight transpose + split: W[K x N] -> B tiles [nt][kc][256][64] ----------------
__global__ __launch_bounds__(256) void k_splitB(
    const float* __restrict__ W, unsigned char* __restrict__ Bhi,
    unsigned char* __restrict__ Blo, int Nreal, int nch) {
    __shared__ float tile[64][33];
    int kb = blockIdx.y * 64;
    int n0 = blockIdx.x * 32;
    int t = threadIdx.x;
    int tx = t & 31, ty = t >> 5;
    #pragma unroll
    for (int i = 0; i < 8; i++) {
        int k = ty + i * 8;
        tile[k][tx] = W[(size_t)(kb + k) * Nreal + n0 + tx];
    }
    __syncthreads();
    int kc = kb >> 6;
    #pragma unroll
    for (int j = 0; j < 4; j++) {
        int nl = ty * 4 + j;
        int n = n0 + nl;
        float x0 = tile[tx * 2][nl];
        float x1 = tile[tx * 2 + 1][nl];
        uint32_t uhi, ulo;
        split2(x0, x1, uhi, ulo);
        int nt = n >> 8, r = n & 255;
        size_t base = ((size_t)(nt * nch + kc)) * B_CH;
        size_t off = base + swz128((uint32_t)(r * 128 + tx * 4));
        *(uint32_t*)(Bhi + off) = uhi;
        *(uint32_t*)(Blo + off) = ulo;
    }
}

// ---------------- bf16x3 GEMM via mma.sync (HMMA): C = split(A) @ split(B)^T ----------------
// Block tile 128(M) x 256(N), BK=64, 512 threads, 2-stage bulk-copy pipeline.
__global__ __launch_bounds__(512) void gemm_mma_bf16x3(
    const unsigned char* __restrict__ Ahi, const unsigned char* __restrict__ Alo,
    const unsigned char* __restrict__ Bhi, const unsigned char* __restrict__ Blo,
    float* __restrict__ C, int Nreal, int nch) {
    extern __shared__ unsigned char smg[];
    uint32_t sb = (smem_u32(smg) + 1023) & ~1023u;
    uint32_t ctrl = sb + 2 * STG;
    int t = threadIdx.x, lane = t & 31, wid = t >> 5;
    int bx = blockIdx.x, by = blockIdx.y;

    if (t == 0) { MBAR_INIT(ctrl + 0, 1); MBAR_INIT(ctrl + 8, 1); }
    __syncthreads();

    const unsigned char* Ah = Ahi + (size_t)by * nch * A_CH;
    const unsigned char* Al = Alo + (size_t)by * nch * A_CH;
    const unsigned char* Bh = Bhi + (size_t)bx * nch * B_CH;
    const unsigned char* Bl = Blo + (size_t)bx * nch * B_CH;

    int wm = wid & 1, wn = wid >> 1;          // 2 x 8 warps; warp tile 64(M) x 32(N)
    int rowA = wm * 64 + (lane & 7) + ((lane >> 3) & 1) * 8;
    int colA = ((lane >> 4) & 1) * 16;
    int rowB = wn * 32 + (lane & 7) + ((lane >> 4) & 1) * 8;
    int colB = ((lane >> 3) & 1) * 16;

    float acc[4][4][4];
    #pragma unroll
    for (int i = 0; i < 4; i++)
        #pragma unroll
        for (int j = 0; j < 4; j++)
            #pragma unroll
            for (int q = 0; q < 4; q++) acc[i][j][q] = 0.f;

    if (t == 0) {
        MBAR_EXPECT_TX(ctrl + 0, STG);
        BULK_LD(sb + 0,     Ah, A_CH, ctrl + 0);
        BULK_LD(sb + 16384, Al, A_CH, ctrl + 0);
        BULK_LD(sb + 32768, Bh, B_CH, ctrl + 0);
        BULK_LD(sb + 65536, Bl, B_CH, ctrl + 0);
    }
    int ph0 = 0, ph1 = 0;
    for (int kc = 0; kc < nch; kc++) {
        int buf = kc & 1;
        if (t == 0 && kc + 1 < nch) {
            uint32_t s = sb + (buf ^ 1) * STG;
            uint32_t mb = ctrl + (buf ^ 1) * 8;
            MBAR_EXPECT_TX(mb, STG);
            BULK_LD(s + 0,     Ah + (size_t)(kc + 1) * A_CH, A_CH, mb);
            BULK_LD(s + 16384, Al + (size_t)(kc + 1) * A_CH, A_CH, mb);
            BULK_LD(s + 32768, Bh + (size_t)(kc + 1) * B_CH, B_CH, mb);
            BULK_LD(s + 65536, Bl + (size_t)(kc + 1) * B_CH, B_CH, mb);
        }
        if (buf == 0) { MBAR_WAIT(ctrl + 0, ph0); ph0 ^= 1; }
        else          { MBAR_WAIT(ctrl + 8, ph1); ph1 ^= 1; }
        uint32_t s = sb + buf * STG;
        uint32_t sAh = s, sAl = s + 16384, sBh = s + 32768, sBl = s + 65536;
        #pragma unroll
        for (int k = 0; k < 4; k++) {
            uint32_t bh[2][4], bl[2][4];
            #pragma unroll
            for (int ib = 0; ib < 2; ib++) {
                uint32_t off = swz128((uint32_t)((rowB + ib * 16) * 128 + k * 32 + colB));
                LDSMX4(bh[ib], sBh + off);
                LDSMX4(bl[ib], sBl + off);
            }
            #pragma unroll
            for (int im = 0; im < 4; im++) {
                uint32_t ah[4], al[4];
                uint32_t off = swz128((uint32_t)((rowA + im * 16) * 128 + k * 32 + colA));
                LDSMX4(ah, sAh + off);
                LDSMX4(al, sAl + off);
                #pragma unroll
                for (int ib = 0; ib < 2; ib++)
                    #pragma unroll
                    for (int hf = 0; hf < 2; hf++)
                        MMA_BF16(acc[im][ib * 2 + hf], ah, bh[ib][2 * hf], bh[ib][2 * hf + 1]);
                #pragma unroll
                for (int ib = 0; ib < 2; ib++)
                    #pragma unroll
                    for (int hf = 0; hf < 2; hf++)
                        MMA_BF16(acc[im][ib * 2 + hf], ah, bl[ib][2 * hf], bl[ib][2 * hf + 1]);
                #pragma unroll
                for (int ib = 0; ib < 2; ib++)
                    #pragma unroll
                    for (int hf = 0; hf < 2; hf++)
                        MMA_BF16(acc[im][ib * 2 + hf], al, bh[ib][2 * hf], bh[ib][2 * hf + 1]);
            }
        }
        __syncthreads();
    }

    // epilogue: direct fp32 stores
    int mBase = by * 128 + wm * 64;
    int nBase = bx * 256 + wn * 32;
    #pragma unroll
    for (int im = 0; im < 4; im++) {
        #pragma unroll
        for (int in = 0; in < 4; in++) {
            int r = mBase + im * 16 + (lane >> 2);
            int c = nBase + in * 8 + (lane & 3) * 2;
            if (c < Nreal) {
                float2 v0 = make_float2(acc[im][in][0], acc[im][in][1]);
                float2 v1 = make_float2(acc[im][in][2], acc[im][in][3]);
                *(float2*)(C + (size_t)r * Nreal + c) = v0;
                *(float2*)(C + (size_t)(r + 8) * Nreal + c) = v1;
            }
        }
    }
}

// ---------------- 3) causal depthwise conv, sliding window: 16 outputs/thread ----------------
// grid: Bn * (Ln/16) * (CONVD/256) blocks of 256 threads; c fastest for coalescing.
__global__ __launch_bounds__(256) void k_conv2(
    const float* __restrict__ cw, const float* __restrict__ cb) {
    int bid = blockIdx.x;
    int c = (bid % 17) * 256 + threadIdx.x;
    int lblk = (bid / 17) & 127;
    int b = bid / (17 * 128);
    int l0 = lblk * 16;
    float w0 = cw[c * 4 + 0], w1 = cw[c * 4 + 1], w2 = cw[c * 4 + 2], w3 = cw[c * 4 + 3];
    float bias = cb[c];
    float x[19];
    #pragma unroll
    for (int i = 0; i < 19; i++) {
        int ls = l0 - 3 + i;
        x[i] = (ls >= 0) ? g_proj[((size_t)(b * Ln + ls)) * PROJW + DINn + c] : 0.f;
    }
    #pragma unroll
    for (int j = 0; j < 16; j++) {
        float acc = fmaf(w0, x[j], fmaf(w1, x[j + 1], fmaf(w2, x[j + 2], fmaf(w3, x[j + 3], bias))));
        g_xbc[((size_t)(b * Ln + l0 + j)) * CONVD + c] = siluf(acc);
    }
}

// ---------------- 4) dt / a ----------------
__global__ __launch_bounds__(256) void k_dt(
    const float* __restrict__ dtb, const float* __restrict__ alog) {
    int idx = blockIdx.x * 256 + threadIdx.x;
    if (idx >= BLn * Hn) return;
    int h = idx & (Hn - 1);
    int bl = idx / Hn;
    float x = g_proj[(size_t)bl * PROJW + (DINn + CONVD) + h] + dtb[h];
    float sp = (x > 20.f) ? x : log1pf(expf(x));
    g_dt[idx] = sp;
    g_a[idx] = -expf(alog[h]) * sp;
}

// ---------------- 5) per-chunk: cumsum, Y_diag + D*xs, local states ----------------
__global__ __launch_bounds__(256) void k_chunk(const float* __restrict__ dskip) {
    extern __shared__ float sm[];
    float* Bsm = sm;
    float* Csm = Bsm + 64 * 129;
    float* Xd  = Csm + 64 * 129;
    float* Ms  = Xd + 64 * 65;
    float* Acs = Ms + 64 * 65;
    float* Dec = Acs + 64;

    int c = blockIdx.x, h = blockIdx.y, b = blockIdx.z;
    int t = threadIdx.x;
    size_t rowbase = ((size_t)(b * Ln + c * Qn)) * CONVD;

    for (int i = t; i < Qn * Nn; i += 256) {
        int s = i >> 7, n = i & 127;
        size_t g = rowbase + (size_t)s * CONVD + DINn;
        Bsm[s * 129 + n] = g_xbc[g + n];
        Csm[s * 129 + n] = g_xbc[g + Nn + n];
    }
    if (t < Qn) Acs[t] = g_a[(size_t)(b * Ln + c * Qn + t) * Hn + h];
    __syncthreads();
    if (t == 0) {
        float r = 0.f;
        for (int i = 0; i < Qn; i++) { r += Acs[i]; Acs[i] = r; }
    }
    __syncthreads();
    if (t < Qn) {
        float aq = Acs[t];
        Dec[t] = expf(Acs[Qn - 1] - aq);
        g_acs[(size_t)(b * Ln + c * Qn + t) * Hn + h] = aq;
        if (t == Qn - 1) g_csum[(size_t)(b * Hn + h) * NCn + c] = aq;
    }
    for (int i = t; i < Qn * Pn; i += 256) {
        int s = i >> 6, p = i & 63;
        float xs = g_xbc[rowbase + (size_t)s * CONVD + h * Pn + p];
        Xd[s * 65 + p] = xs * g_dt[(size_t)(b * Ln + c * Qn + s) * Hn + h];
    }
    __syncthreads();

    {
        int qb = t >> 4, sbq = t & 15;
        int q0 = qb * 4, s0 = sbq * 4;
        float m4[4][4];
        #pragma unroll
        for (int i = 0; i < 4; i++)
            #pragma unroll
            for (int j = 0; j < 4; j++) m4[i][j] = 0.f;
        if (s0 <= q0 + 3) {
            for (int n = 0; n < Nn; n++) {
                float cq[4], bs[4];
                #pragma unroll
                for (int i = 0; i < 4; i++) cq[i] = Csm[(q0 + i) * 129 + n];
                #pragma unroll
                for (int j = 0; j < 4; j++) bs[j] = Bsm[(s0 + j) * 129 + n];
                #pragma unroll
                for (int i = 0; i < 4; i++)
                    #pragma unroll
                    for (int j = 0; j < 4; j++) m4[i][j] = fmaf(cq[i], bs[j], m4[i][j]);
            }
        }
        #pragma unroll
        for (int i = 0; i < 4; i++)
            #pragma unroll
            for (int j = 0; j < 4; j++) {
                int q = q0 + i, s = s0 + j;
                Ms[q * 65 + s] = (s <= q) ? m4[i][j] * expf(Acs[q] - Acs[s]) : 0.f;
            }
    }
    __syncthreads();

    {
        int qb = t >> 4, pb = t & 15;
        int q0 = qb * 4, p0 = pb * 4;
        float y4[4][4];
        #pragma unroll
        for (int i = 0; i < 4; i++)
            #pragma unroll
            for (int j = 0; j < 4; j++) y4[i][j] = 0.f;
        int smax = q0 + 3;
        for (int s = 0; s <= smax; s++) {
            float mv[4], xv[4];
            #pragma unroll
            for (int i = 0; i < 4; i++) mv[i] = Ms[(q0 + i) * 65 + s];
            #pragma unroll
            for (int j = 0; j < 4; j++) xv[j] = Xd[s * 65 + p0 + j];
            #pragma unroll
            for (int i = 0; i < 4; i++)
                #pragma unroll
                for (int j = 0; j < 4; j++) y4[i][j] = fmaf(mv[i], xv[j], y4[i][j]);
        }
        float dsk = dskip[h];
        #pragma unroll
        for (int i = 0; i < 4; i++) {
            int q = q0 + i;
            #pragma unroll
            for (int j = 0; j < 4; j++) {
                int p = p0 + j;
                float xs = g_xbc[rowbase + (size_t)q * CONVD + h * Pn + p];
                g_y[((size_t)(b * Ln + c * Qn + q) * Hn + h) * Pn + p] =
                    y4[i][j] + dsk * xs;
            }
        }
    }

    {
        int pb = t >> 4, nb2 = t & 15;
        int p0 = pb * 4, n0 = nb2 * 8;
        float st[4][8];
        #pragma unroll
        for (int i = 0; i < 4; i++)
            #pragma unroll
            for (int j = 0; j < 8; j++) st[i][j] = 0.f;
        for (int q = 0; q < Qn; q++) {
            float d = Dec[q];
            float xv[4], bv[8];
            #pragma unroll
            for (int i = 0; i < 4; i++) xv[i] = Xd[q * 65 + p0 + i] * d;
            #pragma unroll
            for (int j = 0; j < 8; j++) bv[j] = Bsm[q * 129 + n0 + j];
            #pragma unroll
            for (int i = 0; i < 4; i++)
                #pragma unroll
                for (int j = 0; j < 8; j++) st[i][j] = fmaf(xv[i], bv[j], st[i][j]);
        }
        size_t base = ((size_t)(b * Hn + h) * NCn + c) * (Pn * Nn);
        #pragma unroll
        for (int i = 0; i < 4; i++)
            #pragma unroll
            for (int j = 0; j < 8; j++)
                g_states[base + (size_t)(p0 + i) * Nn + n0 + j] = st[i][j];
    }
}

// ---------------- 6) chunk-level scan, 8-way split over state elements ----------------
__global__ __launch_bounds__(256) void k_scan() {
    int bh = blockIdx.x;
    int e0 = blockIdx.y * 1024 + threadIdx.x;
    float S[4];
    #pragma unroll
    for (int k = 0; k < 4; k++) S[k] = 0.f;
    for (int c = 0; c < NCn; c++) {
        size_t base = ((size_t)bh * NCn + c) * (Pn * Nn);
        #pragma unroll
        for (int k = 0; k < 4; k++) g_statein[base + e0 + k * 256] = S[k];
        float f = expf(g_csum[(size_t)bh * NCn + c]);
        #pragma unroll
        for (int k = 0; k < 4; k++)
            S[k] = fmaf(f, S[k], g_states[base + e0 + k * 256]);
    }
}

// ---------------- 7) Y_off ----------------
__global__ __launch_bounds__(256) void k_yoff() {
    extern __shared__ float sm[];
    float* Ss  = sm;
    float* Csm = Ss + 64 * 129;
    float* Eq  = Csm + 64 * 129;

    int c = blockIdx.x, h = blockIdx.y, b = blockIdx.z;
    int t = threadIdx.x;
    size_t rowbase = ((size_t)(b * Ln + c * Qn)) * CONVD;
    size_t sbase = ((size_t)(b * Hn + h) * NCn + c) * (Pn * Nn);

    for (int i = t; i < Pn * Nn; i += 256) {
        int p = i >> 7, n = i & 127;
        Ss[p * 129 + n] = g_statein[sbase + i];
    }
    for (int i = t; i < Qn * Nn; i += 256) {
        int q = i >> 7, n = i & 127;
        Csm[q * 129 + n] = g_xbc[rowbase + (size_t)q * CONVD + DINn + Nn + n];
    }
    if (t < Qn)
        Eq[t] = expf(g_acs[(size_t)(b * Ln + c * Qn + t) * Hn + h]);
    __syncthreads();

    int qb = t >> 4, pb = t & 15;
    int q0 = qb * 4, p0 = pb * 4;
    float acc[4][4];
    #pragma unroll
    for (int i = 0; i < 4; i++)
        #pragma unroll
        for (int j = 0; j < 4; j++) acc[i][j] = 0.f;
    for (int n = 0; n < Nn; n++) {
        float cq[4], sp[4];
        #pragma unroll
        for (int i = 0; i < 4; i++) cq[i] = Csm[(q0 + i) * 129 + n];
        #pragma unroll
        for (int j = 0; j < 4; j++) sp[j] = Ss[(p0 + j) * 129 + n];
        #pragma unroll
        for (int i = 0; i < 4; i++)
            #pragma unroll
            for (int j = 0; j < 4; j++) acc[i][j] = fmaf(cq[i], sp[j], acc[i][j]);
    }
    #pragma unroll
    for (int i = 0; i < 4; i++) {
        int q = q0 + i;
        float e = Eq[q];
        #pragma unroll
        for (int j = 0; j < 4; j++) {
            int p = p0 + j;
            size_t yi = ((size_t)(b * Ln + c * Qn + q) * Hn + h) * Pn + p;
            g_y[yi] += e * acc[i][j];
        }
    }
}

// ---------------- 8) gated rmsnorm -> bf16 split A tiles (K=4096, nch=64) ----------------
__global__ __launch_bounds__(256) void k_gatenorm_split(
    const float* __restrict__ gw,
    unsigned char* __restrict__ Ahi, unsigned char* __restrict__ Alo) {
    size_t row = blockIdx.x;
    int t = threadIdx.x;
    const float4* py = (const float4*)(g_y + row * DINn);
    const float4* pz = (const float4*)(g_proj + row * PROJW);
    float v[16];
    float ss = 0.f;
    #pragma unroll
    for (int i = 0; i < 4; i++) {
        float4 y4 = py[t * 4 + i];
        float4 z4 = pz[t * 4 + i];
        float x0 = y4.x * siluf(z4.x);
        float x1 = y4.y * siluf(z4.y);
        float x2 = y4.z * siluf(z4.z);
        float x3 = y4.w * siluf(z4.w);
        v[i * 4 + 0] = x0; v[i * 4 + 1] = x1; v[i * 4 + 2] = x2; v[i * 4 + 3] = x3;
        ss += x0 * x0 + x1 * x1 + x2 * x2 + x3 * x3;
    }
    float tot = block_reduce_sum(ss);
    float inv = rsqrtf(tot / (float)DINn + EPSf);
    int mt = (int)(row >> 7), r = (int)(row & 127);
    size_t tb = (size_t)mt * NCH2 * A_CH;
    #pragma unroll
    for (int j = 0; j < 8; j++) {
        int k = t * 16 + j * 2;
        float x0 = v[j * 2] * inv * gw[k];
        float x1 = v[j * 2 + 1] * inv * gw[k + 1];
        uint32_t uhi, ulo;
        split2(x0, x1, uhi, ulo);
        int kc = k >> 6, cc = k & 63;
        size_t off = tb + (size_t)kc * A_CH + swz128((uint32_t)(r * 128 + cc * 2));
        *(uint32_t*)(Ahi + off) = uhi;
        *(uint32_t*)(Alo + off) = ulo;
    }
}

// ---------------- launch ----------------
extern "C" void kernel_launch(void* const* d_in, const int* in_sizes, int n_in,
                              void* d_out, int out_size) {
    const float* hs   = (const float*)d_in[0];
    const float* res  = (const float*)d_in[1];
    const float* nw   = (const float*)d_in[2];
    const float* ipw  = (const float*)d_in[3];
    const float* cw   = (const float*)d_in[4];
    const float* cb   = (const float*)d_in[5];
    const float* alog = (const float*)d_in[6];
    const float* dtb  = (const float*)d_in[7];
    const float* dsk  = (const float*)d_in[8];
    const float* gnw  = (const float*)d_in[9];
    const float* opw  = (const float*)d_in[10];
    float* out = (float*)d_out;

    void *pproj, *pAhi, *pAlo, *pBhi, *pBlo, *pyfb;
    cudaGetSymbolAddress(&pproj, g_proj);
    cudaGetSymbolAddress(&pAhi, g_Ahi);
    cudaGetSymbolAddress(&pAlo, g_Alo);
    cudaGetSymbolAddress(&pBhi, g_Bhi);
    cudaGetSymbolAddress(&pBlo, g_Blo);
    cudaGetSymbolAddress(&pyfb, g_y);

    float* resid_ptr = ((size_t)out_size >= 2ull * BLn * Dn)
                           ? out + (size_t)BLn * Dn
                           : (float*)pyfb;

    const int SMEM_CHUNK = (2 * 64 * 129 + 2 * 64 * 65 + 128) * 4;
    const int SMEM_YOFF  = (2 * 64 * 129 + 64) * 4;
    cudaFuncSetAttribute(k_chunk, cudaFuncAttributeMaxDynamicSharedMemorySize, SMEM_CHUNK);
    cudaFuncSetAttribute(k_yoff,  cudaFuncAttributeMaxDynamicSharedMemorySize, SMEM_YOFF);
    cudaFuncSetAttribute(gemm_mma_bf16x3, cudaFuncAttributeMaxDynamicSharedMemorySize, SMEM_GEMM);

    // 1) resid + rmsnorm -> A tiles (bf16 hi/lo)
    k_add_rmsnorm_split<<<BLn, 256>>>(hs, res, nw, resid_ptr,
                                      (unsigned char*)pAhi, (unsigned char*)pAlo);

    // 2a) split+transpose in_proj_w -> B tiles
    {
        dim3 grid(PROJW / 32, Dn / 64);
        k_splitB<<<grid, 256>>>(ipw, (unsigned char*)pBhi, (unsigned char*)pBlo,
                                PROJW, NCH1);
    }
    // 2b) proj = h @ in_proj_w  (HMMA bf16x3, 128x256 tiles)
    {
        dim3 grid(NT1, MTil);
        gemm_mma_bf16x3<<<grid, 512, SMEM_GEMM>>>(
            (const unsigned char*)pAhi, (const unsigned char*)pAlo,
            (const unsigned char*)pBhi, (const unsigned char*)pBlo,
            (float*)pproj, PROJW, NCH1);
    }

    // 3) conv + silu (sliding window)
    k_conv2<<<Bn * 128 * 17, 256>>>(cw, cb);

    // 4) dt / a
    k_dt<<<(BLn * Hn + 255) / 256, 256>>>(dtb, alog);

    // 5) chunk kernel
    {
        dim3 grid(NCn, Hn, Bn);
        k_chunk<<<grid, 256, SMEM_CHUNK>>>(dsk);
    }

    // 6) inter-chunk scan (8-way split)
    {
        dim3 grid(Bn * Hn, 8);
        k_scan<<<grid, 256>>>();
    }

    // 7) Y_off
    {
        dim3 grid(NCn, Hn, Bn);
        k_yoff<<<grid, 256, SMEM_YOFF>>>();
    }

    // 8) gated rmsnorm -> A tiles (bf16 hi/lo, K=4096)
    k_gatenorm_split<<<BLn, 256>>>(gnw, (unsigned char*)pAhi, (unsigned char*)pAlo);

    // 9a) split+transpose out_proj_w -> B tiles
    {
        dim3 grid(Dn / 32, DINn / 64);
        k_splitB<<<grid, 256>>>(opw, (unsigned char*)pBhi, (unsigned char*)pBlo,
                                Dn, NCH2);
    }
    // 9b) out = yg @ out_proj_w
    {
        dim3 grid(Dn / 256, MTil);
        gemm_mma_bf16x3<<<grid, 512, SMEM_GEMM>>>(
            (const unsigned char*)pAhi, (const unsigned char*)pAlo,
            (const unsigned char*)pBhi, (const unsigned char*)pBlo,
            out, Dn, NCH2);
    }
}

// round 5
// speedup vs baseline: 3.1869x; 1.0927x over previous
#include <cuda_runtime.h>
#include <cuda_fp16.h>
#include <math.h>
#include <stdint.h>

// ---------------- problem constants ----------------
#define Bn    2
#define Ln    2048
#define Dn    2048
#define DINn  4096
#define Nn    128
#define Hn    64
#define Pn    64
#define Kc    4
#define CONVD 4352            // DIN + 2*G*N
#define Qn    64
#define NCn   32
#define PROJW 8512            // 2*DIN + 2*G*N + H
#define DTOFF 8448            // DIN + CONVD
#define BLn   (Bn*Ln)         // 4096
#define EPSf  1e-5f

// GEMM tiling: 128(M) x 256(N) block tile, BK=64, 512 threads, fp16 2-pass
#define A_CH  16384           // bytes per A chunk-tile (128 x 64 fp16, swizzled image)
#define B_CH  32768           // bytes per B chunk-tile (256 x 64 fp16, swizzled image)
#define STG   65536           // stage bytes: Ahi + Alo + B = 16K+16K+32K
#define SMEM_GEMM (1024 + 2*STG + 64)

#define NCH1  32              // in_proj K chunks (2048/64)
#define NT1   34              // in_proj N tiles  (8704/256)
#define NCH2  64              // out_proj K chunks (4096/64)
#define MTil  32              // M tiles (4096/128)

// ---------------- scratch ----------------
__device__ float g_h[(size_t)BLn*Dn];                 // normalized input (fp32, for dt GEMM)
__device__ float g_proj[(size_t)BLn*PROJW];
__device__ float g_xbc[(size_t)BLn*CONVD];
__device__ float g_dt[(size_t)BLn*Hn];
__device__ float g_a[(size_t)BLn*Hn];
__device__ float g_acs[(size_t)BLn*Hn];
__device__ float g_csum[(size_t)Bn*Hn*NCn];
__device__ float g_states[(size_t)Bn*Hn*NCn*Pn*Nn];
__device__ float g_statein[(size_t)Bn*Hn*NCn*Pn*Nn];
__device__ float g_y[(size_t)BLn*DINn];

// fp16 tile buffers (SW128-swizzled SMEM image, chunk-tiled)
__device__ __align__(1024) unsigned char g_Ahi[(size_t)MTil*NCH2*A_CH];
__device__ __align__(1024) unsigned char g_Alo[(size_t)MTil*NCH2*A_CH];
__device__ __align__(1024) unsigned char g_Bf[(size_t)NT1*NCH1*B_CH];

// ---------------- PTX helpers ----------------
__device__ __forceinline__ uint32_t smem_u32(const void* p) {
    uint32_t a;
    asm("{ .reg .u64 t; cvta.to.shared.u64 t, %1; cvt.u32.u64 %0, t; }" : "=r"(a) : "l"(p));
    return a;
}
__device__ __forceinline__ uint32_t swz128(uint32_t o) { return o ^ ((o >> 3) & 0x70); }

#define MBAR_INIT(a, c) \
    asm volatile("mbarrier.init.shared.b64 [%0], %1;" :: "r"(a), "r"(c) : "memory")
#define MBAR_EXPECT_TX(a, b) \
    asm volatile("mbarrier.arrive.expect_tx.shared.b64 _, [%0], %1;" :: "r"(a), "r"(b) : "memory")
#define MBAR_WAIT(a, ph) do { \
    uint32_t _m = (a); uint32_t _p = (ph); uint32_t _d; \
    asm volatile("{\n\t.reg .pred p;\n\t" \
        "mbarrier.try_wait.parity.acquire.cta.shared::cta.b64 p, [%1], %2;\n\t" \
        "selp.b32 %0, 1, 0, p;\n\t}" : "=r"(_d) : "r"(_m), "r"(_p) : "memory"); \
    if (!_d) { \
        asm volatile("{\n\t.reg .pred P1;\n\t" \
            "WL_%=:\n\t" \
            "mbarrier.try_wait.parity.acquire.cta.shared::cta.b64 P1, [%0], %1, 0x989680;\n\t" \
            "@P1 bra.uni WD_%=;\n\t" \
            "bra.uni WL_%=;\n\t" \
            "WD_%=:\n\t}" :: "r"(_m), "r"(_p) : "memory"); \
    } \
} while (0)

#define BULK_LD(sa, gp, bytes, mb) \
    asm volatile("cp.async.bulk.shared::cluster.global.mbarrier::complete_tx::bytes [%0], [%1], %2, [%3];" \
        :: "r"(sa), "l"(gp), "r"(bytes), "r"(mb) : "memory")

#define LDSMX4(r, addr) \
    asm volatile("ldmatrix.sync.aligned.m8n8.x4.shared.b16 {%0,%1,%2,%3}, [%4];" \
        : "=r"((r)[0]), "=r"((r)[1]), "=r"((r)[2]), "=r"((r)[3]) : "r"(addr))

#define MMA_FP16(d, a, b0, b1) \
    asm volatile("mma.sync.aligned.m16n8k16.row.col.f32.f16.f16.f32 " \
        "{%0,%1,%2,%3}, {%4,%5,%6,%7}, {%8,%9}, {%0,%1,%2,%3};" \
        : "+f"((d)[0]), "+f"((d)[1]), "+f"((d)[2]), "+f"((d)[3]) \
        : "r"((a)[0]), "r"((a)[1]), "r"((a)[2]), "r"((a)[3]), "r"(b0), "r"(b1))

// ---------------- misc helpers ----------------
__device__ __forceinline__ float block_reduce_sum(float v) {
    __shared__ float red[32];
    int lane = threadIdx.x & 31, wid = threadIdx.x >> 5;
    #pragma unroll
    for (int o = 16; o; o >>= 1) v += __shfl_down_sync(0xffffffffu, v, o);
    if (lane == 0) red[wid] = v;
    __syncthreads();
    v = (threadIdx.x < (blockDim.x >> 5)) ? red[threadIdx.x] : 0.f;
    if (wid == 0) {
        #pragma unroll
        for (int o = 16; o; o >>= 1) v += __shfl_down_sync(0xffffffffu, v, o);
        if (lane == 0) red[0] = v;
    }
    __syncthreads();
    return red[0];
}
__device__ __forceinline__ float siluf(float x) { return x / (1.f + expf(-x)); }

// fp16 split: x = hi + lo
__device__ __forceinline__ void split2h(float x0, float x1, uint32_t& uhi, uint32_t& ulo) {
    __half h0 = __float2half_rn(x0);
    __half h1 = __float2half_rn(x1);
    __half l0 = __float2half_rn(x0 - __half2float(h0));
    __half l1 = __float2half_rn(x1 - __half2float(h1));
    uhi = ((uint32_t)__half_as_ushort(h1) << 16) | __half_as_ushort(h0);
    ulo = ((uint32_t)__half_as_ushort(l1) << 16) | __half_as_ushort(l0);
}
__device__ __forceinline__ uint32_t pack2h(float x0, float x1) {
    __half h0 = __float2half_rn(x0);
    __half h1 = __float2half_rn(x1);
    return ((uint32_t)__half_as_ushort(h1) << 16) | __half_as_ushort(h0);
}

// ---------------- 1) resid + rmsnorm -> fp32 g_h + fp16 split A tiles ----------------
__global__ __launch_bounds__(256) void k_add_rmsnorm_split(
    const float* __restrict__ hs, const float* __restrict__ res,
    const float* __restrict__ w, float* __restrict__ resid_out,
    unsigned char* __restrict__ Ahi, unsigned char* __restrict__ Alo) {
    size_t row = blockIdx.x;
    int t = threadIdx.x;
    const float4* ph = (const float4*)(hs + row * Dn);
    const float4* pr = (const float4*)(res + row * Dn);
    float4* po = (float4*)(resid_out + row * Dn);
    float v[8];
    float ss = 0.f;
    #pragma unroll
    for (int i = 0; i < 2; i++) {
        float4 a = ph[t * 2 + i], b = pr[t * 2 + i];
        float4 x = make_float4(a.x + b.x, a.y + b.y, a.z + b.z, a.w + b.w);
        po[t * 2 + i] = x;
        v[i * 4 + 0] = x.x; v[i * 4 + 1] = x.y; v[i * 4 + 2] = x.z; v[i * 4 + 3] = x.w;
        ss += x.x * x.x + x.y * x.y + x.z * x.z + x.w * x.w;
    }
    float tot = block_reduce_sum(ss);
    float inv = rsqrtf(tot / (float)Dn + EPSf);
    int mt = (int)(row >> 7), r = (int)(row & 127);
    size_t tb = (size_t)mt * NCH1 * A_CH;
    float4* gh = (float4*)(g_h + row * Dn);
    #pragma unroll
    for (int i = 0; i < 2; i++) {
        float4 x = make_float4(v[i*4]*inv*w[t*8+i*4], v[i*4+1]*inv*w[t*8+i*4+1],
                               v[i*4+2]*inv*w[t*8+i*4+2], v[i*4+3]*inv*w[t*8+i*4+3]);
        gh[t * 2 + i] = x;
        v[i*4] = x.x; v[i*4+1] = x.y; v[i*4+2] = x.z; v[i*4+3] = x.w;
    }
    #pragma unroll
    for (int j = 0; j < 4; j++) {
        int k = t * 8 + j * 2;
        uint32_t uhi, ulo;
        split2h(v[j * 2], v[j * 2 + 1], uhi, ulo);
        int kc = k >> 6, c = k & 63;
        size_t off = tb + (size_t)kc * A_CH + swz128((uint32_t)(r * 128 + c * 2));
        *(uint32_t*)(Ahi + off) = uhi;
        *(uint32_t*)(Alo + off) = ulo;
    }
}

// ---------------- weight transpose to fp16: W[K x N] -> B tiles [nt][kc][256][64] ----------------
__global__ __launch_bounds__(256) void k_splitB(
    const float* __restrict__ W, unsigned char* __restrict__ Bf, int Nreal, int nch) {
    __shared__ float tile[64][33];
    int kb = blockIdx.y * 64;
    int n0 = blockIdx.x * 32;
    int t = threadIdx.x;
    int tx = t & 31, ty = t >> 5;
    #pragma unroll
    for (int i = 0; i < 8; i++) {
        int k = ty + i * 8;
        tile[k][tx] = W[(size_t)(kb + k) * Nreal + n0 + tx];
    }
    __syncthreads();
    int kc = kb >> 6;
    #pragma unroll
    for (int j = 0; j < 4; j++) {
        int nl = ty * 4 + j;
        int n = n0 + nl;
        uint32_t u = pack2h(tile[tx * 2][nl], tile[tx * 2 + 1][nl]);
        int nt = n >> 8, r = n & 255;
        size_t base = ((size_t)(nt * nch + kc)) * B_CH;
        size_t off = base + swz128((uint32_t)(r * 128 + tx * 4));
        *(uint32_t*)(Bf + off) = u;
    }
}

// ---------------- fp16 x2 GEMM via mma.sync: C = (Ahi+Alo) @ B^T-tiles ----------------
// Block tile 128(M) x 256(N), BK=64, 512 threads, 2-stage bulk-copy pipeline.
__global__ __launch_bounds__(512) void gemm_mma_fp16x2(
    const unsigned char* __restrict__ Ahi, const unsigned char* __restrict__ Alo,
    const unsigned char* __restrict__ Bf,
    float* __restrict__ C, int Nreal, int nch) {
    extern __shared__ unsigned char smg[];
    uint32_t sb = (smem_u32(smg) + 1023) & ~1023u;
    uint32_t ctrl = sb + 2 * STG;
    int t = threadIdx.x, lane = t & 31, wid = t >> 5;
    int bx = blockIdx.x, by = blockIdx.y;

    if (t == 0) { MBAR_INIT(ctrl + 0, 1); MBAR_INIT(ctrl + 8, 1); }
    __syncthreads();

    const unsigned char* Ah = Ahi + (size_t)by * nch * A_CH;
    const unsigned char* Al = Alo + (size_t)by * nch * A_CH;
    const unsigned char* Bp = Bf + (size_t)bx * nch * B_CH;

    int wm = wid & 1, wn = wid >> 1;          // 2 x 8 warps; warp tile 64(M) x 32(N)
    int rowA = wm * 64 + (lane & 7) + ((lane >> 3) & 1) * 8;
    int colA = ((lane >> 4) & 1) * 16;
    int rowB = wn * 32 + (lane & 7) + ((lane >> 4) & 1) * 8;
    int colB = ((lane >> 3) & 1) * 16;

    float acc[4][4][4];
    #pragma unroll
    for (int i = 0; i < 4; i++)
        #pragma unroll
        for (int j = 0; j < 4; j++)
            #pragma unroll
            for (int q = 0; q < 4; q++) acc[i][j][q] = 0.f;

    if (t == 0) {
        MBAR_EXPECT_TX(ctrl + 0, STG);
        BULK_LD(sb + 0,     Ah, A_CH, ctrl + 0);
        BULK_LD(sb + 16384, Al, A_CH, ctrl + 0);
        BULK_LD(sb + 32768, Bp, B_CH, ctrl + 0);
    }
    int ph0 = 0, ph1 = 0;
    for (int kc = 0; kc < nch; kc++) {
        int buf = kc & 1;
        if (t == 0 && kc + 1 < nch) {
            uint32_t s = sb + (buf ^ 1) * STG;
            uint32_t mb = ctrl + (buf ^ 1) * 8;
            MBAR_EXPECT_TX(mb, STG);
            BULK_LD(s + 0,     Ah + (size_t)(kc + 1) * A_CH, A_CH, mb);
            BULK_LD(s + 16384, Al + (size_t)(kc + 1) * A_CH, A_CH, mb);
            BULK_LD(s + 32768, Bp + (size_t)(kc + 1) * B_CH, B_CH, mb);
        }
        if (buf == 0) { MBAR_WAIT(ctrl + 0, ph0); ph0 ^= 1; }
        else          { MBAR_WAIT(ctrl + 8, ph1); ph1 ^= 1; }
        uint32_t s = sb + buf * STG;
        uint32_t sAh = s, sAl = s + 16384, sB = s + 32768;
        #pragma unroll
        for (int k = 0; k < 4; k++) {
            uint32_t bh[2][4];
            #pragma unroll
            for (int ib = 0; ib < 2; ib++) {
                uint32_t off = swz128((uint32_t)((rowB + ib * 16) * 128 + k * 32 + colB));
                LDSMX4(bh[ib], sB + off);
            }
            #pragma unroll
            for (int im = 0; im < 4; im++) {
                uint32_t ah[4], al[4];
                uint32_t off = swz128((uint32_t)((rowA + im * 16) * 128 + k * 32 + colA));
                LDSMX4(ah, sAh + off);
                LDSMX4(al, sAl + off);
                #pragma unroll
                for (int ib = 0; ib < 2; ib++)
                    #pragma unroll
                    for (int hf = 0; hf < 2; hf++)
                        MMA_FP16(acc[im][ib * 2 + hf], ah, bh[ib][2 * hf], bh[ib][2 * hf + 1]);
                #pragma unroll
                for (int ib = 0; ib < 2; ib++)
                    #pragma unroll
                    for (int hf = 0; hf < 2; hf++)
                        MMA_FP16(acc[im][ib * 2 + hf], al, bh[ib][2 * hf], bh[ib][2 * hf + 1]);
            }
        }
        __syncthreads();
    }

    // epilogue: direct fp32 stores
    int mBase = by * 128 + wm * 64;
    int nBase = bx * 256 + wn * 32;
    #pragma unroll
    for (int im = 0; im < 4; im++) {
        #pragma unroll
        for (int in = 0; in < 4; in++) {
            int r = mBase + im * 16 + (lane >> 2);
            int c = nBase + in * 8 + (lane & 3) * 2;
            if (c < Nreal) {
                float2 v0 = make_float2(acc[im][in][0], acc[im][in][1]);
                float2 v1 = make_float2(acc[im][in][2], acc[im][in][3]);
                *(float2*)(C + (size_t)r * Nreal + c) = v0;
                *(float2*)(C + (size_t)(r + 8) * Nreal + c) = v1;
            }
        }
    }
}

// ---------------- exact fp32 skinny GEMM for dt columns + softplus ----------------
// grid 64 blocks, each computes 64 rows x 64 dt-cols over K=2048
__global__ __launch_bounds__(256) void k_dtproj(
    const float* __restrict__ ipw, const float* __restrict__ dtb,
    const float* __restrict__ alog) {
    __shared__ float sh[64][68];   // [kk][m]
    __shared__ float sw[64][68];   // [kk][h]
    int m0 = blockIdx.x * 64;
    int t = threadIdx.x;
    int tm = t >> 4, tn = t & 15;  // 16x16 thread grid, each 4x4 outputs
    float acc[4][4];
    #pragma unroll
    for (int i = 0; i < 4; i++)
        #pragma unroll
        for (int j = 0; j < 4; j++) acc[i][j] = 0.f;

    for (int kb = 0; kb < Dn; kb += 64) {
        // load h[64 rows][64 k] -> sh[kk][m]
        #pragma unroll
        for (int i = 0; i < 16; i++) {
            int idx = t + i * 256;
            int m = idx >> 6, kk = idx & 63;
            sh[kk][m] = g_h[(size_t)(m0 + m) * Dn + kb + kk];
        }
        // load W[64 k][64 h] -> sw[kk][h]
        #pragma unroll
        for (int i = 0; i < 16; i++) {
            int idx = t + i * 256;
            int kk = idx >> 6, h = idx & 63;
            sw[kk][h] = ipw[(size_t)(kb + kk) * PROJW + DTOFF + h];
        }
        __syncthreads();
        #pragma unroll 8
        for (int kk = 0; kk < 64; kk++) {
            float4 ar = *(const float4*)&sh[kk][tm * 4];
            float4 br = *(const float4*)&sw[kk][tn * 4];
            float a4[4] = {ar.x, ar.y, ar.z, ar.w};
            float b4[4] = {br.x, br.y, br.z, br.w};
            #pragma unroll
            for (int i = 0; i < 4; i++)
                #pragma unroll
                for (int j = 0; j < 4; j++) acc[i][j] = fmaf(a4[i], b4[j], acc[i][j]);
        }
        __syncthreads();
    }
    #pragma unroll
    for (int i = 0; i < 4; i++) {
        int m = m0 + tm * 4 + i;
        #pragma unroll
        for (int j = 0; j < 4; j++) {
            int h = tn * 4 + j;
            float x = acc[i][j] + dtb[h];
            float sp = (x > 20.f) ? x : log1pf(expf(x));
            g_dt[(size_t)m * Hn + h] = sp;
            g_a[(size_t)m * Hn + h] = -expf(alog[h]) * sp;
        }
    }
}

// ---------------- 3) causal depthwise conv, sliding window: 16 outputs/thread ----------------
__global__ __launch_bounds__(256) void k_conv2(
    const float* __restrict__ cw, const float* __restrict__ cb) {
    int bid = blockIdx.x;
    int c = (bid % 17) * 256 + threadIdx.x;
    int lblk = (bid / 17) & 127;
    int b = bid / (17 * 128);
    int l0 = lblk * 16;
    float w0 = cw[c * 4 + 0], w1 = cw[c * 4 + 1], w2 = cw[c * 4 + 2], w3 = cw[c * 4 + 3];
    float bias = cb[c];
    float x[19];
    #pragma unroll
    for (int i = 0; i < 19; i++) {
        int ls = l0 - 3 + i;
        x[i] = (ls >= 0) ? g_proj[((size_t)(b * Ln + ls)) * PROJW + DINn + c] : 0.f;
    }
    #pragma unroll
    for (int j = 0; j < 16; j++) {
        float acc = fmaf(w0, x[j], fmaf(w1, x[j + 1], fmaf(w2, x[j + 2], fmaf(w3, x[j + 3], bias))));
        g_xbc[((size_t)(b * Ln + l0 + j)) * CONVD + c] = siluf(acc);
    }
}

// ---------------- 5) per-chunk: cumsum, Y_diag + D*xs, local states ----------------
__global__ __launch_bounds__(256) void k_chunk(const float* __restrict__ dskip) {
    extern __shared__ float sm[];
    float* Bsm = sm;
    float* Csm = Bsm + 64 * 129;
    float* Xd  = Csm + 64 * 129;
    float* Ms  = Xd + 64 * 65;
    float* Acs = Ms + 64 * 65;
    float* Dec = Acs + 64;

    int c = blockIdx.x, h = blockIdx.y, b = blockIdx.z;
    int t = threadIdx.x;
    size_t rowbase = ((size_t)(b * Ln + c * Qn)) * CONVD;

    for (int i = t; i < Qn * Nn; i += 256) {
        int s = i >> 7, n = i & 127;
        size_t g = rowbase + (size_t)s * CONVD + DINn;
        Bsm[s * 129 + n] = g_xbc[g + n];
        Csm[s * 129 + n] = g_xbc[g + Nn + n];
    }
    if (t < Qn) Acs[t] = g_a[(size_t)(b * Ln + c * Qn + t) * Hn + h];
    __syncthreads();
    if (t == 0) {
        float r = 0.f;
        for (int i = 0; i < Qn; i++) { r += Acs[i]; Acs[i] = r; }
    }
    __syncthreads();
    if (t < Qn) {
        float aq = Acs[t];
        Dec[t] = expf(Acs[Qn - 1] - aq);
        g_acs[(size_t)(b * Ln + c * Qn + t) * Hn + h] = aq;
        if (t == Qn - 1) g_csum[(size_t)(b * Hn + h) * NCn + c] = aq;
    }
    for (int i = t; i < Qn * Pn; i += 256) {
        int s = i >> 6, p = i & 63;
        float xs = g_xbc[rowbase + (size_t)s * CONVD + h * Pn + p];
        Xd[s * 65 + p] = xs * g_dt[(size_t)(b * Ln + c * Qn + s) * Hn + h];
    }
    __syncthreads();

    {
        int qb = t >> 4, sbq = t & 15;
        int q0 = qb * 4, s0 = sbq * 4;
        float m4[4][4];
        #pragma unroll
        for (int i = 0; i < 4; i++)
            #pragma unroll
            for (int j = 0; j < 4; j++) m4[i][j] = 0.f;
        if (s0 <= q0 + 3) {
            for (int n = 0; n < Nn; n++) {
                float cq[4], bs[4];
                #pragma unroll
                for (int i = 0; i < 4; i++) cq[i] = Csm[(q0 + i) * 129 + n];
                #pragma unroll
                for (int j = 0; j < 4; j++) bs[j] = Bsm[(s0 + j) * 129 + n];
                #pragma unroll
                for (int i = 0; i < 4; i++)
                    #pragma unroll
                    for (int j = 0; j < 4; j++) m4[i][j] = fmaf(cq[i], bs[j], m4[i][j]);
            }
        }
        #pragma unroll
        for (int i = 0; i < 4; i++)
            #pragma unroll
            for (int j = 0; j < 4; j++) {
                int q = q0 + i, s = s0 + j;
                Ms[q * 65 + s] = (s <= q) ? m4[i][j] * expf(Acs[q] - Acs[s]) : 0.f;
            }
    }
    __syncthreads();

    {
        int qb = t >> 4, pb = t & 15;
        int q0 = qb * 4, p0 = pb * 4;
        float y4[4][4];
        #pragma unroll
        for (int i = 0; i < 4; i++)
            #pragma unroll
            for (int j = 0; j < 4; j++) y4[i][j] = 0.f;
        int smax = q0 + 3;
        for (int s = 0; s <= smax; s++) {
            float mv[4], xv[4];
            #pragma unroll
            for (int i = 0; i < 4; i++) mv[i] = Ms[(q0 + i) * 65 + s];
            #pragma unroll
            for (int j = 0; j < 4; j++) xv[j] = Xd[s * 65 + p0 + j];
            #pragma unroll
            for (int i = 0; i < 4; i++)
                #pragma unroll
                for (int j = 0; j < 4; j++) y4[i][j] = fmaf(mv[i], xv[j], y4[i][j]);
        }
        float dsk = dskip[h];
        #pragma unroll
        for (int i = 0; i < 4; i++) {
            int q = q0 + i;
            #pragma unroll
            for (int j = 0; j < 4; j++) {
                int p = p0 + j;
                float xs = g_xbc[rowbase + (size_t)q * CONVD + h * Pn + p];
                g_y[((size_t)(b * Ln + c * Qn + q) * Hn + h) * Pn + p] =
                    y4[i][j] + dsk * xs;
            }
        }
    }

    {
        int pb = t >> 4, nb2 = t & 15;
        int p0 = pb * 4, n0 = nb2 * 8;
        float st[4][8];
        #pragma unroll
        for (int i = 0; i < 4; i++)
            #pragma unroll
            for (int j = 0; j < 8; j++) st[i][j] = 0.f;
        for (int q = 0; q < Qn; q++) {
            float d = Dec[q];
            float xv[4], bv[8];
            #pragma unroll
            for (int i = 0; i < 4; i++) xv[i] = Xd[q * 65 + p0 + i] * d;
            #pragma unroll
            for (int j = 0; j < 8; j++) bv[j] = Bsm[q * 129 + n0 + j];
            #pragma unroll
            for (int i = 0; i < 4; i++)
                #pragma unroll
                for (int j = 0; j < 8; j++) st[i][j] = fmaf(xv[i], bv[j], st[i][j]);
        }
        size_t base = ((size_t)(b * Hn + h) * NCn + c) * (Pn * Nn);
        #pragma unroll
        for (int i = 0; i < 4; i++)
            #pragma unroll
            for (int j = 0; j < 8; j++)
                g_states[base + (size_t)(p0 + i) * Nn + n0 + j] = st[i][j];
    }
}

// ---------------- 6) chunk-level scan, 8-way split over state elements ----------------
__global__ __launch_bounds__(256) void k_scan() {
    int bh = blockIdx.x;
    int e0 = blockIdx.y * 1024 + threadIdx.x;
    float S[4];
    #pragma unroll
    for (int k = 0; k < 4; k++) S[k] = 0.f;
    for (int c = 0; c < NCn; c++) {
        size_t base = ((size_t)bh * NCn + c) * (Pn * Nn);
        #pragma unroll
        for (int k = 0; k < 4; k++) g_statein[base + e0 + k * 256] = S[k];
        float f = expf(g_csum[(size_t)bh * NCn + c]);
        #pragma unroll
        for (int k = 0; k < 4; k++)
            S[k] = fmaf(f, S[k], g_states[base + e0 + k * 256]);
    }
}

// ---------------- 7) Y_off ----------------
__global__ __launch_bounds__(256) void k_yoff() {
    extern __shared__ float sm[];
    float* Ss  = sm;
    float* Csm = Ss + 64 * 129;
    float* Eq  = Csm + 64 * 129;

    int c = blockIdx.x, h = blockIdx.y, b = blockIdx.z;
    int t = threadIdx.x;
    size_t rowbase = ((size_t)(b * Ln + c * Qn)) * CONVD;
    size_t sbase = ((size_t)(b * Hn + h) * NCn + c) * (Pn * Nn);

    for (int i = t; i < Pn * Nn; i += 256) {
        int p = i >> 7, n = i & 127;
        Ss[p * 129 + n] = g_statein[sbase + i];
    }
    for (int i = t; i < Qn * Nn; i += 256) {
        int q = i >> 7, n = i & 127;
        Csm[q * 129 + n] = g_xbc[rowbase + (size_t)q * CONVD + DINn + Nn + n];
    }
    if (t < Qn)
        Eq[t] = expf(g_acs[(size_t)(b * Ln + c * Qn + t) * Hn + h]);
    __syncthreads();

    int qb = t >> 4, pb = t & 15;
    int q0 = qb * 4, p0 = pb * 4;
    float acc[4][4];
    #pragma unroll
    for (int i = 0; i < 4; i++)
        #pragma unroll
        for (int j = 0; j < 4; j++) acc[i][j] = 0.f;
    for (int n = 0; n < Nn; n++) {
        float cq[4], sp[4];
        #pragma unroll
        for (int i = 0; i < 4; i++) cq[i] = Csm[(q0 + i) * 129 + n];
        #pragma unroll
        for (int j = 0; j < 4; j++) sp[j] = Ss[(p0 + j) * 129 + n];
        #pragma unroll
        for (int i = 0; i < 4; i++)
            #pragma unroll
            for (int j = 0; j < 4; j++) acc[i][j] = fmaf(cq[i], sp[j], acc[i][j]);
    }
    #pragma unroll
    for (int i = 0; i < 4; i++) {
        int q = q0 + i;
        float e = Eq[q];
        #pragma unroll
        for (int j = 0; j < 4; j++) {
            int p = p0 + j;
            size_t yi = ((size_t)(b * Ln + c * Qn + q) * Hn + h) * Pn + p;
            g_y[yi] += e * acc[i][j];
        }
    }
}

// ---------------- 8) gated rmsnorm -> fp16 split A tiles (K=4096, nch=64) ----------------
__global__ __launch_bounds__(256) void k_gatenorm_split(
    const float* __restrict__ gw,
    unsigned char* __restrict__ Ahi, unsigned char* __restrict__ Alo) {
    size_t row = blockIdx.x;
    int t = threadIdx.x;
    const float4* py = (const float4*)(g_y + row * DINn);
    const float4* pz = (const float4*)(g_proj + row * PROJW);
    float v[16];
    float ss = 0.f;
    #pragma unroll
    for (int i = 0; i < 4; i++) {
        float4 y4 = py[t * 4 + i];
        float4 z4 = pz[t * 4 + i];
        float x0 = y4.x * siluf(z4.x);
        float x1 = y4.y * siluf(z4.y);
        float x2 = y4.z * siluf(z4.z);
        float x3 = y4.w * siluf(z4.w);
        v[i * 4 + 0] = x0; v[i * 4 + 1] = x1; v[i * 4 + 2] = x2; v[i * 4 + 3] = x3;
        ss += x0 * x0 + x1 * x1 + x2 * x2 + x3 * x3;
    }
    float tot = block_reduce_sum(ss);
    float inv = rsqrtf(tot / (float)DINn + EPSf);
    int mt = (int)(row >> 7), r = (int)(row & 127);
    size_t tb = (size_t)mt * NCH2 * A_CH;
    #pragma unroll
    for (int j = 0; j < 8; j++) {
        int k = t * 16 + j * 2;
        float x0 = v[j * 2] * inv * gw[k];
        float x1 = v[j * 2 + 1] * inv * gw[k + 1];
        uint32_t uhi, ulo;
        split2h(x0, x1, uhi, ulo);
        int kc = k >> 6, cc = k & 63;
        size_t off = tb + (size_t)kc * A_CH + swz128((uint32_t)(r * 128 + cc * 2));
        *(uint32_t*)(Ahi + off) = uhi;
        *(uint32_t*)(Alo + off) = ulo;
    }
}

// ---------------- launch ----------------
extern "C" void kernel_launch(void* const* d_in, const int* in_sizes, int n_in,
                              void* d_out, int out_size) {
    const float* hs   = (const float*)d_in[0];
    const float* res  = (const float*)d_in[1];
    const float* nw   = (const float*)d_in[2];
    const float* ipw  = (const float*)d_in[3];
    const float* cw   = (const float*)d_in[4];
    const float* cb   = (const float*)d_in[5];
    const float* alog = (const float*)d_in[6];
    const float* dtb  = (const float*)d_in[7];
    const float* dsk  = (const float*)d_in[8];
    const float* gnw  = (const float*)d_in[9];
    const float* opw  = (const float*)d_in[10];
    float* out = (float*)d_out;

    void *pproj, *pAhi, *pAlo, *pBf, *pyfb;
    cudaGetSymbolAddress(&pproj, g_proj);
    cudaGetSymbolAddress(&pAhi, g_Ahi);
    cudaGetSymbolAddress(&pAlo, g_Alo);
    cudaGetSymbolAddress(&pBf, g_Bf);
    cudaGetSymbolAddress(&pyfb, g_y);

    float* resid_ptr = ((size_t)out_size >= 2ull * BLn * Dn)
                           ? out + (size_t)BLn * Dn
                           : (float*)pyfb;

    const int SMEM_CHUNK = (2 * 64 * 129 + 2 * 64 * 65 + 128) * 4;
    const int SMEM_YOFF  = (2 * 64 * 129 + 64) * 4;
    cudaFuncSetAttribute(k_chunk, cudaFuncAttributeMaxDynamicSharedMemorySize, SMEM_CHUNK);
    cudaFuncSetAttribute(k_yoff,  cudaFuncAttributeMaxDynamicSharedMemorySize, SMEM_YOFF);
    cudaFuncSetAttribute(gemm_mma_fp16x2, cudaFuncAttributeMaxDynamicSharedMemorySize, SMEM_GEMM);

    // 1) resid + rmsnorm -> fp32 g_h + fp16 A tiles
    k_add_rmsnorm_split<<<BLn, 256>>>(hs, res, nw, resid_ptr,
                                      (unsigned char*)pAhi, (unsigned char*)pAlo);

    // 1b) exact fp32 dt projection + softplus (precision-critical path)
    k_dtproj<<<BLn / 64, 256>>>(ipw, dtb, alog);

    // 2a) transpose in_proj_w -> fp16 B tiles
    {
        dim3 grid(PROJW / 32, Dn / 64);
        k_splitB<<<grid, 256>>>(ipw, (unsigned char*)pBf, PROJW, NCH1);
    }
    // 2b) proj = h @ in_proj_w  (fp16 x2 HMMA)
    {
        dim3 grid(NT1, MTil);
        gemm_mma_fp16x2<<<grid, 512, SMEM_GEMM>>>(
            (const unsigned char*)pAhi, (const unsigned char*)pAlo,
            (const unsigned char*)pBf, (float*)pproj, PROJW, NCH1);
    }

    // 3) conv + silu (sliding window)
    k_conv2<<<Bn * 128 * 17, 256>>>(cw, cb);

    // 5) chunk kernel
    {
        dim3 grid(NCn, Hn, Bn);
        k_chunk<<<grid, 256, SMEM_CHUNK>>>(dsk);
    }

    // 6) inter-chunk scan (8-way split)
    {
        dim3 grid(Bn * Hn, 8);
        k_scan<<<grid, 256>>>();
    }

    // 7) Y_off
    {
        dim3 grid(NCn, Hn, Bn);
        k_yoff<<<grid, 256, SMEM_YOFF>>>();
    }

    // 8) gated rmsnorm -> fp16 A tiles (K=4096)
    k_gatenorm_split<<<BLn, 256>>>(gnw, (unsigned char*)pAhi, (unsigned char*)pAlo);

    // 9a) transpose out_proj_w -> fp16 B tiles
    {
        dim3 grid(Dn / 32, DINn / 64);
        k_splitB<<<grid, 256>>>(opw, (unsigned char*)pBf, Dn, NCH2);
    }
    // 9b) out = yg @ out_proj_w
    {
        dim3 grid(Dn / 256, MTil);
        gemm_mma_fp16x2<<<grid, 512, SMEM_GEMM>>>(
            (const unsigned char*)pAhi, (const unsigned char*)pAlo,
            (const unsigned char*)pBf, out, Dn, NCH2);
    }
}

// round 6
// speedup vs baseline: 3.9478x; 1.2388x over previous
#include <cuda_runtime.h>
#include <cuda_fp16.h>
#include <math.h>
#include <stdint.h>

// ---------------- problem constants ----------------
#define Bn    2
#define Ln    2048
#define Dn    2048
#define DINn  4096
#define Nn    128
#define Hn    64
#define Pn    64
#define Kc    4
#define CONVD 4352            // DIN + 2*G*N
#define Qn    64
#define NCn   32
#define PROJW 8512            // 2*DIN + 2*G*N + H
#define DTOFF 8448            // DIN + CONVD
#define BLn   (Bn*Ln)         // 4096
#define EPSf  1e-5f

// GEMM tiling: 128(M) x 256(N) block tile, BK=64, 512 threads, fp16 single-pass
#define A_CH  16384           // bytes per A chunk-tile (128 x 64 fp16, swizzled image)
#define B_CH  32768           // bytes per B chunk-tile (256 x 64 fp16, swizzled image)
#define STG   49152           // stage bytes: A + B
#define NSTAGE 3
#define SMEM_GEMM (1024 + NSTAGE*STG + 64)

#define NCH1  32              // in_proj K chunks (2048/64)
#define NT1   34              // in_proj N tiles  (8704/256)
#define NCH2  64              // out_proj K chunks (4096/64)
#define MTil  32              // M tiles (4096/128)

// ---------------- scratch ----------------
__device__ float g_h[(size_t)BLn*Dn];                 // normalized input (fp32, for dt GEMM)
__device__ float g_proj[(size_t)BLn*PROJW];
__device__ float g_xbc[(size_t)BLn*CONVD];
__device__ float g_dt[(size_t)BLn*Hn];
__device__ float g_a[(size_t)BLn*Hn];
__device__ float g_acs[(size_t)BLn*Hn];
__device__ float g_csum[(size_t)Bn*Hn*NCn];
__device__ float g_states[(size_t)Bn*Hn*NCn*Pn*Nn];
__device__ float g_statein[(size_t)Bn*Hn*NCn*Pn*Nn];
__device__ float g_y[(size_t)BLn*DINn];

// fp16 tile buffers (SW128-swizzled SMEM image, chunk-tiled)
__device__ __align__(1024) unsigned char g_Af[(size_t)MTil*NCH2*A_CH];
__device__ __align__(1024) unsigned char g_Bf[(size_t)NT1*NCH1*B_CH];

// ---------------- PTX helpers ----------------
__device__ __forceinline__ uint32_t smem_u32(const void* p) {
    uint32_t a;
    asm("{ .reg .u64 t; cvta.to.shared.u64 t, %1; cvt.u32.u64 %0, t; }" : "=r"(a) : "l"(p));
    return a;
}
__device__ __forceinline__ uint32_t swz128(uint32_t o) { return o ^ ((o >> 3) & 0x70); }

#define MBAR_INIT(a, c) \
    asm volatile("mbarrier.init.shared.b64 [%0], %1;" :: "r"(a), "r"(c) : "memory")
#define MBAR_EXPECT_TX(a, b) \
    asm volatile("mbarrier.arrive.expect_tx.shared.b64 _, [%0], %1;" :: "r"(a), "r"(b) : "memory")
#define MBAR_WAIT(a, ph) do { \
    uint32_t _m = (a); uint32_t _p = (ph); uint32_t _d; \
    asm volatile("{\n\t.reg .pred p;\n\t" \
        "mbarrier.try_wait.parity.acquire.cta.shared::cta.b64 p, [%1], %2;\n\t" \
        "selp.b32 %0, 1, 0, p;\n\t}" : "=r"(_d) : "r"(_m), "r"(_p) : "memory"); \
    if (!_d) { \
        asm volatile("{\n\t.reg .pred P1;\n\t" \
            "WL_%=:\n\t" \
            "mbarrier.try_wait.parity.acquire.cta.shared::cta.b64 P1, [%0], %1, 0x989680;\n\t" \
            "@P1 bra.uni WD_%=;\n\t" \
            "bra.uni WL_%=;\n\t" \
            "WD_%=:\n\t}" :: "r"(_m), "r"(_p) : "memory"); \
    } \
} while (0)

#define BULK_LD(sa, gp, bytes, mb) \
    asm volatile("cp.async.bulk.shared::cluster.global.mbarrier::complete_tx::bytes [%0], [%1], %2, [%3];" \
        :: "r"(sa), "l"(gp), "r"(bytes), "r"(mb) : "memory")

#define LDSMX4(r, addr) \
    asm volatile("ldmatrix.sync.aligned.m8n8.x4.shared.b16 {%0,%1,%2,%3}, [%4];" \
        : "=r"((r)[0]), "=r"((r)[1]), "=r"((r)[2]), "=r"((r)[3]) : "r"(addr))

#define MMA_FP16(d, a, b0, b1) \
    asm volatile("mma.sync.aligned.m16n8k16.row.col.f32.f16.f16.f32 " \
        "{%0,%1,%2,%3}, {%4,%5,%6,%7}, {%8,%9}, {%0,%1,%2,%3};" \
        : "+f"((d)[0]), "+f"((d)[1]), "+f"((d)[2]), "+f"((d)[3]) \
        : "r"((a)[0]), "r"((a)[1]), "r"((a)[2]), "r"((a)[3]), "r"(b0), "r"(b1))

// ---------------- misc helpers ----------------
__device__ __forceinline__ float block_reduce_sum(float v) {
    __shared__ float red[32];
    int lane = threadIdx.x & 31, wid = threadIdx.x >> 5;
    #pragma unroll
    for (int o = 16; o; o >>= 1) v += __shfl_down_sync(0xffffffffu, v, o);
    if (lane == 0) red[wid] = v;
    __syncthreads();
    v = (threadIdx.x < (blockDim.x >> 5)) ? red[threadIdx.x] : 0.f;
    if (wid == 0) {
        #pragma unroll
        for (int o = 16; o; o >>= 1) v += __shfl_down_sync(0xffffffffu, v, o);
        if (lane == 0) red[0] = v;
    }
    __syncthreads();
    return red[0];
}
__device__ __forceinline__ float siluf(float x) { return x / (1.f + expf(-x)); }

__device__ __forceinline__ uint32_t pack2h(float x0, float x1) {
    __half h0 = __float2half_rn(x0);
    __half h1 = __float2half_rn(x1);
    return ((uint32_t)__half_as_ushort(h1) << 16) | __half_as_ushort(h0);
}

// ---------------- 1) resid + rmsnorm -> fp32 g_h + fp16 A tiles ----------------
__global__ __launch_bounds__(256) void k_add_rmsnorm_split(
    const float* __restrict__ hs, const float* __restrict__ res,
    const float* __restrict__ w, float* __restrict__ resid_out,
    unsigned char* __restrict__ Af) {
    size_t row = blockIdx.x;
    int t = threadIdx.x;
    const float4* ph = (const float4*)(hs + row * Dn);
    const float4* pr = (const float4*)(res + row * Dn);
    float4* po = (float4*)(resid_out + row * Dn);
    float v[8];
    float ss = 0.f;
    #pragma unroll
    for (int i = 0; i < 2; i++) {
        float4 a = ph[t * 2 + i], b = pr[t * 2 + i];
        float4 x = make_float4(a.x + b.x, a.y + b.y, a.z + b.z, a.w + b.w);
        po[t * 2 + i] = x;
        v[i * 4 + 0] = x.x; v[i * 4 + 1] = x.y; v[i * 4 + 2] = x.z; v[i * 4 + 3] = x.w;
        ss += x.x * x.x + x.y * x.y + x.z * x.z + x.w * x.w;
    }
    float tot = block_reduce_sum(ss);
    float inv = rsqrtf(tot / (float)Dn + EPSf);
    int mt = (int)(row >> 7), r = (int)(row & 127);
    size_t tb = (size_t)mt * NCH1 * A_CH;
    float4* gh = (float4*)(g_h + row * Dn);
    #pragma unroll
    for (int i = 0; i < 2; i++) {
        float4 x = make_float4(v[i*4]*inv*w[t*8+i*4], v[i*4+1]*inv*w[t*8+i*4+1],
                               v[i*4+2]*inv*w[t*8+i*4+2], v[i*4+3]*inv*w[t*8+i*4+3]);
        gh[t * 2 + i] = x;
        v[i*4] = x.x; v[i*4+1] = x.y; v[i*4+2] = x.z; v[i*4+3] = x.w;
    }
    #pragma unroll
    for (int j = 0; j < 4; j++) {
        int k = t * 8 + j * 2;
        uint32_t u = pack2h(v[j * 2], v[j * 2 + 1]);
        int kc = k >> 6, c = k & 63;
        size_t off = tb + (size_t)kc * A_CH + swz128((uint32_t)(r * 128 + c * 2));
        *(uint32_t*)(Af + off) = u;
    }
}

// ---------------- weight transpose to fp16: W[K x N] -> B tiles [nt][kc][256][64] ----------------
__global__ __launch_bounds__(256) void k_splitB(
    const float* __restrict__ W, unsigned char* __restrict__ Bf, int Nreal, int nch) {
    __shared__ float tile[64][33];
    int kb = blockIdx.y * 64;
    int n0 = blockIdx.x * 32;
    int t = threadIdx.x;
    int tx = t & 31, ty = t >> 5;
    #pragma unroll
    for (int i = 0; i < 8; i++) {
        int k = ty + i * 8;
        tile[k][tx] = W[(size_t)(kb + k) * Nreal + n0 + tx];
    }
    __syncthreads();
    int kc = kb >> 6;
    #pragma unroll
    for (int j = 0; j < 4; j++) {
        int nl = ty * 4 + j;
        int n = n0 + nl;
        uint32_t u = pack2h(tile[tx * 2][nl], tile[tx * 2 + 1][nl]);
        int nt = n >> 8, r = n & 255;
        size_t base = ((size_t)(nt * nch + kc)) * B_CH;
        size_t off = base + swz128((uint32_t)(r * 128 + tx * 4));
        *(uint32_t*)(Bf + off) = u;
    }
}

// ---------------- fp16 single-pass GEMM via mma.sync: C = A @ B^T-tiles ----------------
// Block tile 128(M) x 256(N), BK=64, 512 threads, 3-stage bulk-copy pipeline.
__global__ __launch_bounds__(512) void gemm_mma_fp16(
    const unsigned char* __restrict__ Af, const unsigned char* __restrict__ Bf,
    float* __restrict__ C, int Nreal, int nch) {
    extern __shared__ unsigned char smg[];
    uint32_t sb = (smem_u32(smg) + 1023) & ~1023u;
    uint32_t ctrl = sb + NSTAGE * STG;
    int t = threadIdx.x, lane = t & 31, wid = t >> 5;
    int bx = blockIdx.x, by = blockIdx.y;

    if (t == 0) { MBAR_INIT(ctrl + 0, 1); MBAR_INIT(ctrl + 8, 1); MBAR_INIT(ctrl + 16, 1); }
    __syncthreads();

    const unsigned char* Ap = Af + (size_t)by * nch * A_CH;
    const unsigned char* Bp = Bf + (size_t)bx * nch * B_CH;

    int wm = wid & 1, wn = wid >> 1;          // 2 x 8 warps; warp tile 64(M) x 32(N)
    int rowA = wm * 64 + (lane & 7) + ((lane >> 3) & 1) * 8;
    int colA = ((lane >> 4) & 1) * 16;
    int rowB = wn * 32 + (lane & 7) + ((lane >> 4) & 1) * 8;
    int colB = ((lane >> 3) & 1) * 16;

    float acc[4][4][4];
    #pragma unroll
    for (int i = 0; i < 4; i++)
        #pragma unroll
        for (int j = 0; j < 4; j++)
            #pragma unroll
            for (int q = 0; q < 4; q++) acc[i][j][q] = 0.f;

    // prologue: load chunks 0 and 1
    if (t == 0) {
        MBAR_EXPECT_TX(ctrl + 0, STG);
        BULK_LD(sb + 0,     Ap, A_CH, ctrl + 0);
        BULK_LD(sb + 16384, Bp, B_CH, ctrl + 0);
        if (nch > 1) {
            MBAR_EXPECT_TX(ctrl + 8, STG);
            BULK_LD(sb + STG + 0,     Ap + A_CH, A_CH, ctrl + 8);
            BULK_LD(sb + STG + 16384, Bp + B_CH, B_CH, ctrl + 8);
        }
    }
    int ph[NSTAGE] = {0, 0, 0};
    for (int kc = 0; kc < nch; kc++) {
        int slot = kc % NSTAGE;
        MBAR_WAIT(ctrl + slot * 8, ph[slot]);
        ph[slot] ^= 1;
        uint32_t s = sb + slot * STG;
        uint32_t sA = s, sB = s + 16384;
        #pragma unroll
        for (int k = 0; k < 4; k++) {
            uint32_t bh[2][4];
            #pragma unroll
            for (int ib = 0; ib < 2; ib++) {
                uint32_t off = swz128((uint32_t)((rowB + ib * 16) * 128 + k * 32 + colB));
                LDSMX4(bh[ib], sB + off);
            }
            #pragma unroll
            for (int im = 0; im < 4; im++) {
                uint32_t ah[4];
                uint32_t off = swz128((uint32_t)((rowA + im * 16) * 128 + k * 32 + colA));
                LDSMX4(ah, sA + off);
                #pragma unroll
                for (int ib = 0; ib < 2; ib++)
                    #pragma unroll
                    for (int hf = 0; hf < 2; hf++)
                        MMA_FP16(acc[im][ib * 2 + hf], ah, bh[ib][2 * hf], bh[ib][2 * hf + 1]);
            }
        }
        __syncthreads();
        if (t == 0 && kc + 2 < nch) {
            int ns = (kc + 2) % NSTAGE;
            uint32_t d = sb + ns * STG;
            uint32_t mb = ctrl + ns * 8;
            MBAR_EXPECT_TX(mb, STG);
            BULK_LD(d + 0,     Ap + (size_t)(kc + 2) * A_CH, A_CH, mb);
            BULK_LD(d + 16384, Bp + (size_t)(kc + 2) * B_CH, B_CH, mb);
        }
    }

    // epilogue: direct fp32 stores
    int mBase = by * 128 + wm * 64;
    int nBase = bx * 256 + wn * 32;
    #pragma unroll
    for (int im = 0; im < 4; im++) {
        #pragma unroll
        for (int in = 0; in < 4; in++) {
            int r = mBase + im * 16 + (lane >> 2);
            int c = nBase + in * 8 + (lane & 3) * 2;
            if (c < Nreal) {
                float2 v0 = make_float2(acc[im][in][0], acc[im][in][1]);
                float2 v1 = make_float2(acc[im][in][2], acc[im][in][3]);
                *(float2*)(C + (size_t)r * Nreal + c) = v0;
                *(float2*)(C + (size_t)(r + 8) * Nreal + c) = v1;
            }
        }
    }
}

// ---------------- exact fp32 skinny GEMM for dt columns + softplus ----------------
__global__ __launch_bounds__(256) void k_dtproj(
    const float* __restrict__ ipw, const float* __restrict__ dtb,
    const float* __restrict__ alog) {
    __shared__ float sh[64][68];   // [kk][m]
    __shared__ float sw[64][68];   // [kk][h]
    int m0 = blockIdx.x * 64;
    int t = threadIdx.x;
    int tm = t >> 4, tn = t & 15;
    float acc[4][4];
    #pragma unroll
    for (int i = 0; i < 4; i++)
        #pragma unroll
        for (int j = 0; j < 4; j++) acc[i][j] = 0.f;

    for (int kb = 0; kb < Dn; kb += 64) {
        #pragma unroll
        for (int i = 0; i < 16; i++) {
            int idx = t + i * 256;
            int m = idx >> 6, kk = idx & 63;
            sh[kk][m] = g_h[(size_t)(m0 + m) * Dn + kb + kk];
        }
        #pragma unroll
        for (int i = 0; i < 16; i++) {
            int idx = t + i * 256;
            int kk = idx >> 6, h = idx & 63;
            sw[kk][h] = ipw[(size_t)(kb + kk) * PROJW + DTOFF + h];
        }
        __syncthreads();
        #pragma unroll 8
        for (int kk = 0; kk < 64; kk++) {
            float4 ar = *(const float4*)&sh[kk][tm * 4];
            float4 br = *(const float4*)&sw[kk][tn * 4];
            float a4[4] = {ar.x, ar.y, ar.z, ar.w};
            float b4[4] = {br.x, br.y, br.z, br.w};
            #pragma unroll
            for (int i = 0; i < 4; i++)
                #pragma unroll
                for (int j = 0; j < 4; j++) acc[i][j] = fmaf(a4[i], b4[j], acc[i][j]);
        }
        __syncthreads();
    }
    #pragma unroll
    for (int i = 0; i < 4; i++) {
        int m = m0 + tm * 4 + i;
        #pragma unroll
        for (int j = 0; j < 4; j++) {
            int h = tn * 4 + j;
            float x = acc[i][j] + dtb[h];
            float sp = (x > 20.f) ? x : log1pf(expf(x));
            g_dt[(size_t)m * Hn + h] = sp;
            g_a[(size_t)m * Hn + h] = -expf(alog[h]) * sp;
        }
    }
}

// ---------------- 3) causal depthwise conv, sliding window ----------------
__global__ __launch_bounds__(256) void k_conv2(
    const float* __restrict__ cw, const float* __restrict__ cb) {
    int bid = blockIdx.x;
    int c = (bid % 17) * 256 + threadIdx.x;
    int lblk = (bid / 17) & 127;
    int b = bid / (17 * 128);
    int l0 = lblk * 16;
    float w0 = cw[c * 4 + 0], w1 = cw[c * 4 + 1], w2 = cw[c * 4 + 2], w3 = cw[c * 4 + 3];
    float bias = cb[c];
    float x[19];
    #pragma unroll
    for (int i = 0; i < 19; i++) {
        int ls = l0 - 3 + i;
        x[i] = (ls >= 0) ? g_proj[((size_t)(b * Ln + ls)) * PROJW + DINn + c] : 0.f;
    }
    #pragma unroll
    for (int j = 0; j < 16; j++) {
        float acc = fmaf(w0, x[j], fmaf(w1, x[j + 1], fmaf(w2, x[j + 2], fmaf(w3, x[j + 3], bias))));
        g_xbc[((size_t)(b * Ln + l0 + j)) * CONVD + c] = siluf(acc);
    }
}

// ---------------- 5) per-chunk: cumsum, Y_diag + D*xs, local states ----------------
__global__ __launch_bounds__(256) void k_chunk(const float* __restrict__ dskip) {
    extern __shared__ float sm[];
    float* Bsm = sm;
    float* Csm = Bsm + 64 * 129;
    float* Xd  = Csm + 64 * 129;
    float* Ms  = Xd + 64 * 65;
    float* Acs = Ms + 64 * 65;
    float* Dec = Acs + 64;

    int c = blockIdx.x, h = blockIdx.y, b = blockIdx.z;
    int t = threadIdx.x;
    size_t rowbase = ((size_t)(b * Ln + c * Qn)) * CONVD;

    for (int i = t; i < Qn * Nn; i += 256) {
        int s = i >> 7, n = i & 127;
        size_t g = rowbase + (size_t)s * CONVD + DINn;
        Bsm[s * 129 + n] = g_xbc[g + n];
        Csm[s * 129 + n] = g_xbc[g + Nn + n];
    }
    if (t < Qn) Acs[t] = g_a[(size_t)(b * Ln + c * Qn + t) * Hn + h];
    __syncthreads();
    if (t == 0) {
        float r = 0.f;
        for (int i = 0; i < Qn; i++) { r += Acs[i]; Acs[i] = r; }
    }
    __syncthreads();
    if (t < Qn) {
        float aq = Acs[t];
        Dec[t] = expf(Acs[Qn - 1] - aq);
        g_acs[(size_t)(b * Ln + c * Qn + t) * Hn + h] = aq;
        if (t == Qn - 1) g_csum[(size_t)(b * Hn + h) * NCn + c] = aq;
    }
    for (int i = t; i < Qn * Pn; i += 256) {
        int s = i >> 6, p = i & 63;
        float xs = g_xbc[rowbase + (size_t)s * CONVD + h * Pn + p];
        Xd[s * 65 + p] = xs * g_dt[(size_t)(b * Ln + c * Qn + s) * Hn + h];
    }
    __syncthreads();

    {
        int qb = t >> 4, sbq = t & 15;
        int q0 = qb * 4, s0 = sbq * 4;
        float m4[4][4];
        #pragma unroll
        for (int i = 0; i < 4; i++)
            #pragma unroll
            for (int j = 0; j < 4; j++) m4[i][j] = 0.f;
        if (s0 <= q0 + 3) {
            for (int n = 0; n < Nn; n++) {
                float cq[4], bs[4];
                #pragma unroll
                for (int i = 0; i < 4; i++) cq[i] = Csm[(q0 + i) * 129 + n];
                #pragma unroll
                for (int j = 0; j < 4; j++) bs[j] = Bsm[(s0 + j) * 129 + n];
                #pragma unroll
                for (int i = 0; i < 4; i++)
                    #pragma unroll
                    for (int j = 0; j < 4; j++) m4[i][j] = fmaf(cq[i], bs[j], m4[i][j]);
            }
        }
        #pragma unroll
        for (int i = 0; i < 4; i++)
            #pragma unroll
            for (int j = 0; j < 4; j++) {
                int q = q0 + i, s = s0 + j;
                Ms[q * 65 + s] = (s <= q) ? m4[i][j] * expf(Acs[q] - Acs[s]) : 0.f;
            }
    }
    __syncthreads();

    {
        int qb = t >> 4, pb = t & 15;
        int q0 = qb * 4, p0 = pb * 4;
        float y4[4][4];
        #pragma unroll
        for (int i = 0; i < 4; i++)
            #pragma unroll
            for (int j = 0; j < 4; j++) y4[i][j] = 0.f;
        int smax = q0 + 3;
        for (int s = 0; s <= smax; s++) {
            float mv[4], xv[4];
            #pragma unroll
            for (int i = 0; i < 4; i++) mv[i] = Ms[(q0 + i) * 65 + s];
            #pragma unroll
            for (int j = 0; j < 4; j++) xv[j] = Xd[s * 65 + p0 + j];
            #pragma unroll
            for (int i = 0; i < 4; i++)
                #pragma unroll
                for (int j = 0; j < 4; j++) y4[i][j] = fmaf(mv[i], xv[j], y4[i][j]);
        }
        float dsk = dskip[h];
        #pragma unroll
        for (int i = 0; i < 4; i++) {
            int q = q0 + i;
            #pragma unroll
            for (int j = 0; j < 4; j++) {
                int p = p0 + j;
                float xs = g_xbc[rowbase + (size_t)q * CONVD + h * Pn + p];
                g_y[((size_t)(b * Ln + c * Qn + q) * Hn + h) * Pn + p] =
                    y4[i][j] + dsk * xs;
            }
        }
    }

    {
        int pb = t >> 4, nb2 = t & 15;
        int p0 = pb * 4, n0 = nb2 * 8;
        float st[4][8];
        #pragma unroll
        for (int i = 0; i < 4; i++)
            #pragma unroll
            for (int j = 0; j < 8; j++) st[i][j] = 0.f;
        for (int q = 0; q < Qn; q++) {
            float d = Dec[q];
            float xv[4], bv[8];
            #pragma unroll
            for (int i = 0; i < 4; i++) xv[i] = Xd[q * 65 + p0 + i] * d;
            #pragma unroll
            for (int j = 0; j < 8; j++) bv[j] = Bsm[q * 129 + n0 + j];
            #pragma unroll
            for (int i = 0; i < 4; i++)
                #pragma unroll
                for (int j = 0; j < 8; j++) st[i][j] = fmaf(xv[i], bv[j], st[i][j]);
        }
        size_t base = ((size_t)(b * Hn + h) * NCn + c) * (Pn * Nn);
        #pragma unroll
        for (int i = 0; i < 4; i++)
            #pragma unroll
            for (int j = 0; j < 8; j++)
                g_states[base + (size_t)(p0 + i) * Nn + n0 + j] = st[i][j];
    }
}

// ---------------- 6) chunk-level scan, 8-way split over state elements ----------------
__global__ __launch_bounds__(256) void k_scan() {
    int bh = blockIdx.x;
    int e0 = blockIdx.y * 1024 + threadIdx.x;
    float S[4];
    #pragma unroll
    for (int k = 0; k < 4; k++) S[k] = 0.f;
    for (int c = 0; c < NCn; c++) {
        size_t base = ((size_t)bh * NCn + c) * (Pn * Nn);
        #pragma unroll
        for (int k = 0; k < 4; k++) g_statein[base + e0 + k * 256] = S[k];
        float f = expf(g_csum[(size_t)bh * NCn + c]);
        #pragma unroll
        for (int k = 0; k < 4; k++)
            S[k] = fmaf(f, S[k], g_states[base + e0 + k * 256]);
    }
}

// ---------------- 7) Y_off ----------------
__global__ __launch_bounds__(256) void k_yoff() {
    extern __shared__ float sm[];
    float* Ss  = sm;
    float* Csm = Ss + 64 * 129;
    float* Eq  = Csm + 64 * 129;

    int c = blockIdx.x, h = blockIdx.y, b = blockIdx.z;
    int t = threadIdx.x;
    size_t rowbase = ((size_t)(b * Ln + c * Qn)) * CONVD;
    size_t sbase = ((size_t)(b * Hn + h) * NCn + c) * (Pn * Nn);

    for (int i = t; i < Pn * Nn; i += 256) {
        int p = i >> 7, n = i & 127;
        Ss[p * 129 + n] = g_statein[sbase + i];
    }
    for (int i = t; i < Qn * Nn; i += 256) {
        int q = i >> 7, n = i & 127;
        Csm[q * 129 + n] = g_xbc[rowbase + (size_t)q * CONVD + DINn + Nn + n];
    }
    if (t < Qn)
        Eq[t] = expf(g_acs[(size_t)(b * Ln + c * Qn + t) * Hn + h]);
    __syncthreads();

    int qb = t >> 4, pb = t & 15;
    int q0 = qb * 4, p0 = pb * 4;
    float acc[4][4];
    #pragma unroll
    for (int i = 0; i < 4; i++)
        #pragma unroll
        for (int j = 0; j < 4; j++) acc[i][j] = 0.f;
    for (int n = 0; n < Nn; n++) {
        float cq[4], sp[4];
        #pragma unroll
        for (int i = 0; i < 4; i++) cq[i] = Csm[(q0 + i) * 129 + n];
        #pragma unroll
        for (int j = 0; j < 4; j++) sp[j] = Ss[(p0 + j) * 129 + n];
        #pragma unroll
        for (int i = 0; i < 4; i++)
            #pragma unroll
            for (int j = 0; j < 4; j++) acc[i][j] = fmaf(cq[i], sp[j], acc[i][j]);
    }
    #pragma unroll
    for (int i = 0; i < 4; i++) {
        int q = q0 + i;
        float e = Eq[q];
        #pragma unroll
        for (int j = 0; j < 4; j++) {
            int p = p0 + j;
            size_t yi = ((size_t)(b * Ln + c * Qn + q) * Hn + h) * Pn + p;
            g_y[yi] += e * acc[i][j];
        }
    }
}

// ---------------- 8) gated rmsnorm -> fp16 A tiles (K=4096, nch=64) ----------------
__global__ __launch_bounds__(256) void k_gatenorm_split(
    const float* __restrict__ gw, unsigned char* __restrict__ Af) {
    size_t row = blockIdx.x;
    int t = threadIdx.x;
    const float4* py = (const float4*)(g_y + row * DINn);
    const float4* pz = (const float4*)(g_proj + row * PROJW);
    float v[16];
    float ss = 0.f;
    #pragma unroll
    for (int i = 0; i < 4; i++) {
        float4 y4 = py[t * 4 + i];
        float4 z4 = pz[t * 4 + i];
        float x0 = y4.x * siluf(z4.x);
        float x1 = y4.y * siluf(z4.y);
        float x2 = y4.z * siluf(z4.z);
        float x3 = y4.w * siluf(z4.w);
        v[i * 4 + 0] = x0; v[i * 4 + 1] = x1; v[i * 4 + 2] = x2; v[i * 4 + 3] = x3;
        ss += x0 * x0 + x1 * x1 + x2 * x2 + x3 * x3;
    }
    float tot = block_reduce_sum(ss);
    float inv = rsqrtf(tot / (float)DINn + EPSf);
    int mt = (int)(row >> 7), r = (int)(row & 127);
    size_t tb = (size_t)mt * NCH2 * A_CH;
    #pragma unroll
    for (int j = 0; j < 8; j++) {
        int k = t * 16 + j * 2;
        uint32_t u = pack2h(v[j * 2] * inv * gw[k], v[j * 2 + 1] * inv * gw[k + 1]);
        int kc = k >> 6, cc = k & 63;
        size_t off = tb + (size_t)kc * A_CH + swz128((uint32_t)(r * 128 + cc * 2));
        *(uint32_t*)(Af + off) = u;
    }
}

// ---------------- launch ----------------
extern "C" void kernel_launch(void* const* d_in, const int* in_sizes, int n_in,
                              void* d_out, int out_size) {
    const float* hs   = (const float*)d_in[0];
    const float* res  = (const float*)d_in[1];
    const float* nw   = (const float*)d_in[2];
    const float* ipw  = (const float*)d_in[3];
    const float* cw   = (const float*)d_in[4];
    const float* cb   = (const float*)d_in[5];
    const float* alog = (const float*)d_in[6];
    const float* dtb  = (const float*)d_in[7];
    const float* dsk  = (const float*)d_in[8];
    const float* gnw  = (const float*)d_in[9];
    const float* opw  = (const float*)d_in[10];
    float* out = (float*)d_out;

    void *pproj, *pAf, *pBf, *pyfb;
    cudaGetSymbolAddress(&pproj, g_proj);
    cudaGetSymbolAddress(&pAf, g_Af);
    cudaGetSymbolAddress(&pBf, g_Bf);
    cudaGetSymbolAddress(&pyfb, g_y);

    float* resid_ptr = ((size_t)out_size >= 2ull * BLn * Dn)
                           ? out + (size_t)BLn * Dn
                           : (float*)pyfb;

    const int SMEM_CHUNK = (2 * 64 * 129 + 2 * 64 * 65 + 128) * 4;
    const int SMEM_YOFF  = (2 * 64 * 129 + 64) * 4;
    cudaFuncSetAttribute(k_chunk, cudaFuncAttributeMaxDynamicSharedMemorySize, SMEM_CHUNK);
    cudaFuncSetAttribute(k_yoff,  cudaFuncAttributeMaxDynamicSharedMemorySize, SMEM_YOFF);
    cudaFuncSetAttribute(gemm_mma_fp16, cudaFuncAttributeMaxDynamicSharedMemorySize, SMEM_GEMM);

    // 1) resid + rmsnorm -> fp32 g_h + fp16 A tiles
    k_add_rmsnorm_split<<<BLn, 256>>>(hs, res, nw, resid_ptr, (unsigned char*)pAf);

    // 1b) exact fp32 dt projection + softplus (precision-critical path)
    k_dtproj<<<BLn / 64, 256>>>(ipw, dtb, alog);

    // 2a) transpose in_proj_w -> fp16 B tiles
    {
        dim3 grid(PROJW / 32, Dn / 64);
        k_splitB<<<grid, 256>>>(ipw, (unsigned char*)pBf, PROJW, NCH1);
    }
    // 2b) proj = h @ in_proj_w  (fp16 single-pass HMMA)
    {
        dim3 grid(NT1, MTil);
        gemm_mma_fp16<<<grid, 512, SMEM_GEMM>>>(
            (const unsigned char*)pAf, (const unsigned char*)pBf,
            (float*)pproj, PROJW, NCH1);
    }

    // 3) conv + silu (sliding window)
    k_conv2<<<Bn * 128 * 17, 256>>>(cw, cb);

    // 5) chunk kernel
    {
        dim3 grid(NCn, Hn, Bn);
        k_chunk<<<grid, 256, SMEM_CHUNK>>>(dsk);
    }

    // 6) inter-chunk scan (8-way split)
    {
        dim3 grid(Bn * Hn, 8);
        k_scan<<<grid, 256>>>();
    }

    // 7) Y_off
    {
        dim3 grid(NCn, Hn, Bn);
        k_yoff<<<grid, 256, SMEM_YOFF>>>();
    }

    // 8) gated rmsnorm -> fp16 A tiles (K=4096)
    k_gatenorm_split<<<BLn, 256>>>(gnw, (unsigned char*)pAf);

    // 9a) transpose out_proj_w -> fp16 B tiles
    {
        dim3 grid(Dn / 32, DINn / 64);
        k_splitB<<<grid, 256>>>(opw, (unsigned char*)pBf, Dn, NCH2);
    }
    // 9b) out = yg @ out_proj_w
    {
        dim3 grid(Dn / 256, MTil);
        gemm_mma_fp16<<<grid, 512, SMEM_GEMM>>>(
            (const unsigned char*)pAf, (const unsigned char*)pBf,
            out, Dn, NCH2);
    }
}